// round 9
// baseline (speedup 1.0000x reference)
#include <cuda_runtime.h>
#include <cuda_bf16.h>
#include <math.h>

// Problem constants (from reference)
#define N_NODES_MAX 100000
#define E_MAX       1600000
#define IN_C 128
#define H1   71
#define H2   82
// padded row strides (floats), multiples of 4 for float4 alignment
#define NP1  72   // H1 padded  (18 quads)
#define NP2  84   // H2 padded  (21 quads)

// ------------------- device scratch (static, no allocation) -------------------
__device__ int   g_is64;
__device__ int   g_deg[N_NODES_MAX];
__device__ float g_dinv[N_NODES_MAX];
__device__ int   g_rowoff[N_NODES_MAX + 1];
__device__ int   g_cursor[N_NODES_MAX];
__device__ int   g_csr[E_MAX];
__device__ int   g_src[E_MAX];
__device__ int   g_dst[E_MAX];
__device__ int   g_bsum[256];
__device__ float g_bufA[(size_t)N_NODES_MAX * NP2];  // GEMM outputs (scaled rows)
__device__ float g_bufB[(size_t)N_NODES_MAX * NP2];  // gather outputs

// ------------------- packed f32x2 helpers -------------------
__device__ __forceinline__ unsigned long long pk2(float lo, float hi) {
    unsigned long long d;
    asm("mov.b64 %0, {%1, %2};" : "=l"(d) : "f"(lo), "f"(hi));
    return d;
}
__device__ __forceinline__ void upk2(float& lo, float& hi, unsigned long long v) {
    asm("mov.b64 {%0, %1}, %2;" : "=f"(lo), "=f"(hi) : "l"(v));
}
#define FMA2(d, a, b, c) \
    asm("fma.rn.f32x2 %0, %1, %2, %3;" : "=l"(d) : "l"(a), "l"(b), "l"(c))
#define MUL2(d, a, b) \
    asm("mul.rn.f32x2 %0, %1, %2;" : "=l"(d) : "l"(a), "l"(b))

// ------------------- setup kernels -------------------
__global__ void k_init_deg(const int* __restrict__ ei32, int E, int n) {
    int i = blockIdx.x * blockDim.x + threadIdx.x;
    if (i < n) g_deg[i] = 0;
    if (blockIdx.x == 0 && threadIdx.x == 0) {
        // dtype sniff: int64 indices < 1e5 have zero odd words
        int all0 = 1;
        int m = (E > 64) ? 64 : E;
        for (int q = 0; q < m; q++)
            if (ei32[2 * q + 1] != 0) { all0 = 0; break; }
        g_is64 = all0;
    }
}

__global__ void k_deg_count(const void* __restrict__ ei, int E, int n) {
    int i = blockIdx.x * blockDim.x + threadIdx.x;
    if (i < E) {
        int s, d;
        if (g_is64) {
            s = (int)((const long long*)ei)[i];
            d = (int)((const long long*)ei)[(size_t)E + i];
        } else {
            s = ((const int*)ei)[i];
            d = ((const int*)ei)[(size_t)E + i];
        }
        s = min(max(s, 0), n - 1);
        d = min(max(d, 0), n - 1);
        g_src[i] = s;
        g_dst[i] = d;
        atomicAdd(&g_deg[d], 1);
    }
}

// pass 1: per-block (1024 elems) sums of deg; also compute dinv.
__global__ void __launch_bounds__(1024) k_scan1(int n) {
    __shared__ int wsum[32];
    int t = threadIdx.x, lane = t & 31, wid = t >> 5;
    int i = blockIdx.x * 1024 + t;
    int v = (i < n) ? g_deg[i] : 0;
    if (i < n) g_dinv[i] = rsqrtf((float)v + 1.0f);
    int x = v;
#pragma unroll
    for (int off = 16; off; off >>= 1) x += __shfl_down_sync(0xffffffffu, x, off);
    if (lane == 0) wsum[wid] = x;
    __syncthreads();
    if (wid == 0) {
        int y = wsum[lane];
#pragma unroll
        for (int off = 16; off; off >>= 1) y += __shfl_down_sync(0xffffffffu, y, off);
        if (lane == 0) g_bsum[blockIdx.x] = y;
    }
}

// pass 2: exclusive scan of block sums (nb <= 256), single block of 256.
__global__ void __launch_bounds__(256) k_scan2(int nb) {
    __shared__ int wsum[8];
    int t = threadIdx.x, lane = t & 31, wid = t >> 5;
    int v = (t < nb) ? g_bsum[t] : 0;
    int x = v;
#pragma unroll
    for (int off = 1; off < 32; off <<= 1) {
        int y = __shfl_up_sync(0xffffffffu, x, off);
        if (lane >= off) x += y;
    }
    if (lane == 31) wsum[wid] = x;
    __syncthreads();
    if (wid == 0 && lane < 8) {
        int w = wsum[lane];
        int xx = w;
#pragma unroll
        for (int off = 1; off < 8; off <<= 1) {
            int y = __shfl_up_sync(0xffu, xx, off);
            if (lane >= off) xx += y;
        }
        wsum[lane] = xx - w;  // exclusive warp offsets
    }
    __syncthreads();
    if (t < nb) g_bsum[t] = wsum[wid] + (x - v);
}

// pass 3: local exclusive scan + block offset -> rowoff, cursor.
__global__ void __launch_bounds__(1024) k_scan3(int n) {
    __shared__ int wsum[32];
    int t = threadIdx.x, lane = t & 31, wid = t >> 5;
    int i = blockIdx.x * 1024 + t;
    int v = (i < n) ? g_deg[i] : 0;
    int x = v;
#pragma unroll
    for (int off = 1; off < 32; off <<= 1) {
        int y = __shfl_up_sync(0xffffffffu, x, off);
        if (lane >= off) x += y;
    }
    if (lane == 31) wsum[wid] = x;
    __syncthreads();
    if (wid == 0) {
        int w = wsum[lane];
        int xx = w;
#pragma unroll
        for (int off = 1; off < 32; off <<= 1) {
            int y = __shfl_up_sync(0xffffffffu, xx, off);
            if (lane >= off) xx += y;
        }
        wsum[lane] = xx - w;
    }
    __syncthreads();
    int excl = g_bsum[blockIdx.x] + wsum[wid] + (x - v);
    if (i < n) {
        g_rowoff[i] = excl;
        g_cursor[i] = excl;
    }
    if (i == n - 1) g_rowoff[n] = excl + v;
}

__global__ void k_fill(int E) {
    int i = blockIdx.x * blockDim.x + threadIdx.x;
    if (i < E) {
        int d = g_dst[i];
        int p = atomicAdd(&g_cursor[d], 1);
        g_csr[p] = g_src[i];
    }
}

// ------------------- pipelined register-tiled GEMM -------------------
// g_bufA[node, :NP) = dinv[node] * (X[node,:] @ W), rows padded to NP.
// Block: NQ x TY threads; thread (tx,ty) computes TM nodes x quad tx.
// Double-buffered smem tiles (one __syncthreads per tile, next tile's LDG/STS
// overlap current tile's FFMA2s). x stored pre-packed (v,v); x read via LDS.128.
template <int NQ, int TY, int TM, int KREAL, int KLOOP, int LDX,
          int NREAL, int NP, bool FROM_PARAM, int MAXB>
__global__ void __launch_bounds__(NQ * TY, MAXB)
k_gemm_pipe(const float* __restrict__ Xp, const float* __restrict__ W, int n) {
    constexpr int KK = 16;
    constexpr int NT = (KLOOP + KK - 1) / KK;  // k tiles
    constexpr int BM = TY * TM;
    constexpr int BMP = BM + 2;                // keep 16B row alignment
    constexpr int THREADS = NQ * TY;
    __shared__ __align__(16) float2 xs2[2][KK][BMP];
    __shared__ __align__(16) float4 ws4[2][KK][NQ];
    const float* X = FROM_PARAM ? Xp : (const float*)g_bufB;
    const int tx = threadIdx.x, ty = threadIdx.y;
    const int t = ty * NQ + tx;
    const int node0 = blockIdx.x * BM;

    unsigned long long acc[2 * TM];
#pragma unroll
    for (int h = 0; h < 2 * TM; h++) acc[h] = 0ull;

    // ---- tile loader (zero-fills k/N overrun) ----
    auto load_tile = [&](int tile, int buf) {
        const int k0 = tile * KK;
        // x tile: pre-packed (v,v), transposed
        for (int idx = t; idx < BM * KK; idx += THREADS) {
            int nl = idx >> 4;
            int kk = idx & 15;
            int k = k0 + kk;
            int node = node0 + nl;
            float v = 0.0f;
            if (k < LDX && node < n) v = X[(size_t)node * LDX + k];
            xs2[buf][kk][nl] = make_float2(v, v);
        }
        // W chunk, zero-padded in k and N
        for (int idx = t; idx < KK * NQ; idx += THREADS) {
            int kk = idx / NQ;
            int q = idx - kk * NQ;
            int j = q * 4;
            int gk = k0 + kk;
            float4 w = make_float4(0.f, 0.f, 0.f, 0.f);
            if (gk < KREAL) {
                const float* wr = W + (size_t)gk * NREAL;
                if (j + 0 < NREAL) w.x = wr[j + 0];
                if (j + 1 < NREAL) w.y = wr[j + 1];
                if (j + 2 < NREAL) w.z = wr[j + 2];
                if (j + 3 < NREAL) w.w = wr[j + 3];
            }
            ws4[buf][kk][q] = w;
        }
    };

    load_tile(0, 0);
    __syncthreads();

    for (int tile = 0; tile < NT; tile++) {
        const int cur = tile & 1;
        if (tile + 1 < NT) load_tile(tile + 1, cur ^ 1);
#pragma unroll
        for (int kk = 0; kk < KK; kk++) {
            ulonglong2 w = *reinterpret_cast<const ulonglong2*>(&ws4[cur][kk][tx]);
#pragma unroll
            for (int j = 0; j < TM / 2; j++) {
                ulonglong2 xp = *reinterpret_cast<const ulonglong2*>(
                    &xs2[cur][kk][ty * TM + 2 * j]);
                FMA2(acc[4 * j + 0], xp.x, w.x, acc[4 * j + 0]);
                FMA2(acc[4 * j + 1], xp.x, w.y, acc[4 * j + 1]);
                FMA2(acc[4 * j + 2], xp.y, w.x, acc[4 * j + 2]);
                FMA2(acc[4 * j + 3], xp.y, w.y, acc[4 * j + 3]);
            }
        }
        __syncthreads();
    }

    float4* Y4 = (float4*)g_bufA;
#pragma unroll
    for (int m = 0; m < TM; m++) {
        int node = node0 + ty * TM + m;
        if (node < n) {
            float di = g_dinv[node];
            unsigned long long di2 = pk2(di, di);
            unsigned long long r0, r1;
            MUL2(r0, acc[2 * m], di2);
            MUL2(r1, acc[2 * m + 1], di2);
            float4 o;
            upk2(o.x, o.y, r0);
            upk2(o.z, o.w, r1);
            Y4[(size_t)node * NQ + tx] = o;
        }
    }
}

// Layer-3 GEMM (N=1): y[node] = dinv[node] * (h2[node,:] . W3), smem-tiled x.
__global__ void __launch_bounds__(256)
k_gemm_n1(const float* __restrict__ W, int n) {
    constexpr int BM = 256, KK = 32, KLOOP = NP2, KREAL = H2;
    __shared__ float xs[KK][BM + 1];
    __shared__ float ws[KLOOP];
    const float* X = (const float*)g_bufB;
    const int t = threadIdx.x;
    const int node0 = blockIdx.x * BM;
    if (t < KLOOP) ws[t] = (t < KREAL) ? W[t] : 0.0f;
    __syncthreads();
    float acc = 0.0f;
    for (int k0 = 0; k0 < KLOOP; k0 += KK) {
        const int kc = (KLOOP - k0 < KK) ? (KLOOP - k0) : KK;
        for (int idx = t; idx < BM * KK; idx += 256) {
            int nl = idx >> 5;
            int kk = idx & 31;
            int node = node0 + nl;
            float v = 0.0f;
            if (kk < kc && node < n) v = X[(size_t)node * NP2 + k0 + kk];
            xs[kk][nl] = v;
        }
        __syncthreads();
#pragma unroll 8
        for (int kk = 0; kk < kc; kk++) acc += xs[kk][t] * ws[k0 + kk];
        __syncthreads();
    }
    const int node = node0 + t;
    if (node < n) g_bufA[node] = acc * g_dinv[node];
}

// ------------------- gather: flat mapping (node = gt/NQ4), 100% lane use -------------------
// g_bufB[i,:] = dinv[i] * (sum_{s in N(i)} y[s,:] + y[i,:]) + b  (optional relu)
template <int NQ4, int NREAL, bool RELU>
__global__ void __launch_bounds__(256)
k_gather_flat(const float* __restrict__ b, int n) {
    const int gt = blockIdx.x * blockDim.x + threadIdx.x;
    const int node = gt / NQ4;
    const int lane = gt - node * NQ4;  // 0..NQ4-1
    if (node >= n) return;
    const float4* __restrict__ xw = (const float4*)g_bufA;  // row stride NQ4 quads

    float4 a0 = make_float4(0.f, 0.f, 0.f, 0.f);
    float4 a1 = make_float4(0.f, 0.f, 0.f, 0.f);
    float4 a2 = make_float4(0.f, 0.f, 0.f, 0.f);
    float4 a3 = make_float4(0.f, 0.f, 0.f, 0.f);

    const int beg = g_rowoff[node];
    const int end = g_rowoff[node + 1];
    int e = beg;
    for (; e + 3 < end; e += 4) {
        int s0 = g_csr[e];
        int s1 = g_csr[e + 1];
        int s2 = g_csr[e + 2];
        int s3 = g_csr[e + 3];
        float4 v0 = __ldg(&xw[(size_t)s0 * NQ4 + lane]);
        float4 v1 = __ldg(&xw[(size_t)s1 * NQ4 + lane]);
        float4 v2 = __ldg(&xw[(size_t)s2 * NQ4 + lane]);
        float4 v3 = __ldg(&xw[(size_t)s3 * NQ4 + lane]);
        a0.x += v0.x; a0.y += v0.y; a0.z += v0.z; a0.w += v0.w;
        a1.x += v1.x; a1.y += v1.y; a1.z += v1.z; a1.w += v1.w;
        a2.x += v2.x; a2.y += v2.y; a2.z += v2.z; a2.w += v2.w;
        a3.x += v3.x; a3.y += v3.y; a3.z += v3.z; a3.w += v3.w;
    }
    for (; e < end; e++) {
        int s0 = g_csr[e];
        float4 v0 = __ldg(&xw[(size_t)s0 * NQ4 + lane]);
        a0.x += v0.x; a0.y += v0.y; a0.z += v0.z; a0.w += v0.w;
    }
    float4 yi = __ldg(&xw[(size_t)node * NQ4 + lane]);
    a0.x += a1.x + a2.x + a3.x + yi.x;
    a0.y += a1.y + a2.y + a3.y + yi.y;
    a0.z += a1.z + a2.z + a3.z + yi.z;
    a0.w += a1.w + a2.w + a3.w + yi.w;
    const float di = g_dinv[node];
    const int c = lane * 4;
    float4 bv = make_float4(0.f, 0.f, 0.f, 0.f);
    if (c + 0 < NREAL) bv.x = __ldg(&b[c + 0]);
    if (c + 1 < NREAL) bv.y = __ldg(&b[c + 1]);
    if (c + 2 < NREAL) bv.z = __ldg(&b[c + 2]);
    if (c + 3 < NREAL) bv.w = __ldg(&b[c + 3]);
    float4 v;
    v.x = fmaf(di, a0.x, bv.x);
    v.y = fmaf(di, a0.y, bv.y);
    v.z = fmaf(di, a0.z, bv.z);
    v.w = fmaf(di, a0.w, bv.w);
    if (RELU) {
        v.x = fmaxf(v.x, 0.f); v.y = fmaxf(v.y, 0.f);
        v.z = fmaxf(v.z, 0.f); v.w = fmaxf(v.w, 0.f);
    }
    // pad cols stay zero (keeps next layer's pad-K columns inert)
    if (c + 0 >= NREAL) v.x = 0.f;
    if (c + 1 >= NREAL) v.y = 0.f;
    if (c + 2 >= NREAL) v.z = 0.f;
    if (c + 3 >= NREAL) v.w = 0.f;
    ((float4*)g_bufB)[(size_t)node * NQ4 + lane] = v;
}

// Final layer (scalar): lanes over edges, shfl reduce; writes d_out.
__global__ void __launch_bounds__(256)
k_gather_out(const float* __restrict__ b, float* __restrict__ out, int n) {
    const int node = (blockIdx.x * blockDim.x + threadIdx.x) >> 5;
    if (node >= n) return;
    const int lane = threadIdx.x & 31;
    const float* y = (const float*)g_bufA;  // stride 1, already dinv_s-scaled
    const int beg = g_rowoff[node];
    const int end = g_rowoff[node + 1];
    float acc = 0.0f;
    for (int e = beg + lane; e < end; e += 32) {
        int s = g_csr[e];
        acc += __ldg(&y[s]);
    }
#pragma unroll
    for (int off = 16; off; off >>= 1) acc += __shfl_down_sync(0xffffffffu, acc, off);
    if (lane == 0) {
        out[node] = g_dinv[node] * (acc + y[node]) + __ldg(&b[0]);
    }
}

// ------------------- launcher (pure kernel launches; capture-safe) -------------------
extern "C" void kernel_launch(void* const* d_in, const int* in_sizes, int n_in,
                              void* d_out, int out_size) {
    const float* x   = (const float*)d_in[0];
    const void*  ei  = d_in[1];
    const float* W1  = (const float*)d_in[2];
    const float* b1  = (const float*)d_in[3];
    const float* W2  = (const float*)d_in[4];
    const float* b2  = (const float*)d_in[5];
    const float* W3  = (const float*)d_in[6];
    const float* b3  = (const float*)d_in[7];
    float*       out = (float*)d_out;

    const int n = in_sizes[0] / IN_C;
    const int E = in_sizes[1] / 2;

    const int TB = 256;
    const int nb_nodes = (n + TB - 1) / TB;
    const int nb_edges = (E + TB - 1) / TB;
    const int nb_warps = (n * 32 + TB - 1) / TB;
    const int nb_scan  = (n + 1023) / 1024;
    const int nb_n1    = (n + 255) / 256;

    // Layer 1 GEMM: NQ=18 x TY=14, TM=8 -> BM=112, 252 thr
    const int nb_gemm1 = (n + 111) / 112;
    // Layer 2 GEMM: NQ=21 x TY=12, TM=8 -> BM=96, 252 thr
    const int nb_gemm2 = (n + 95) / 96;
    // Flat gathers
    const int nb_gath1 = ((long long)n * (NP1 / 4) + TB - 1) / TB;
    const int nb_gath2 = ((long long)n * (NP2 / 4) + TB - 1) / TB;

    // CSR build + layer-1 GEMM interleaved so gemm1 is launch index 3 (ncu target).
    k_init_deg<<<nb_nodes, TB>>>((const int*)ei, E, n);        // 0
    k_deg_count<<<nb_edges, TB>>>(ei, E, n);                   // 1
    k_scan1<<<nb_scan, 1024>>>(n);                             // 2 (dinv ready)
    k_gemm_pipe<18, 14, 8, IN_C, IN_C, IN_C, H1, NP1, true, 3>
        <<<nb_gemm1, dim3(18, 14)>>>(x, W1, n);                // 3 <- profiled
    k_scan2<<<1, 256>>>(nb_scan);                              // 4
    k_scan3<<<nb_scan, 1024>>>(n);                             // 5
    k_fill<<<nb_edges, TB>>>(E);                               // 6

    // Layer 1 gather: bufA -> bufB [stride 72]
    k_gather_flat<NP1 / 4, H1, true><<<nb_gath1, TB>>>(b1, n);

    // Layer 2 GEMM + gather [stride 84]
    k_gemm_pipe<21, 12, 8, H1, NP1, NP1, H2, NP2, false, 3>
        <<<nb_gemm2, dim3(21, 12)>>>(nullptr, W2, n);
    k_gather_flat<NP2 / 4, H2, false><<<nb_gath2, TB>>>(b2, n);

    // Layer 3: y = dinv*(h2@W3) [stride 1] ; gather+bias -> out
    k_gemm_n1<<<nb_n1, 256>>>(W3, n);
    k_gather_out<<<nb_warps, TB>>>(b3, out, n);
}

// round 11
// speedup vs baseline: 1.0455x; 1.0455x over previous
#include <cuda_runtime.h>
#include <cuda_bf16.h>
#include <math.h>

// Problem constants (from reference)
#define N_NODES_MAX 100000
#define E_MAX       1600000
#define IN_C 128
#define H1   71
#define H2   82
// padded row strides (floats), multiples of 4 for float4 alignment
#define NP1  72   // H1 padded  (18 quads)
#define NP2  84   // H2 padded  (21 quads)

// ------------------- device scratch (static, no allocation) -------------------
__device__ int   g_is64;
__device__ int   g_deg[N_NODES_MAX];
__device__ float g_dinv[N_NODES_MAX];
__device__ int   g_rowoff[N_NODES_MAX + 1];
__device__ int   g_cursor[N_NODES_MAX];
__device__ int   g_csr[E_MAX];
__device__ int   g_src[E_MAX];
__device__ int   g_dst[E_MAX];
__device__ int   g_bsum[256];
__device__ float g_bufA[(size_t)N_NODES_MAX * NP2];  // GEMM outputs (UNscaled xw rows)
__device__ float g_bufB[(size_t)N_NODES_MAX * NP2];  // gather outputs

// ------------------- packed f32x2 helpers -------------------
__device__ __forceinline__ unsigned long long pk2(float lo, float hi) {
    unsigned long long d;
    asm("mov.b64 %0, {%1, %2};" : "=l"(d) : "f"(lo), "f"(hi));
    return d;
}
__device__ __forceinline__ void upk2(float& lo, float& hi, unsigned long long v) {
    asm("mov.b64 {%0, %1}, %2;" : "=f"(lo), "=f"(hi) : "l"(v));
}
#define FMA2(d, a, b, c) \
    asm("fma.rn.f32x2 %0, %1, %2, %3;" : "=l"(d) : "l"(a), "l"(b), "l"(c))

// ------------------- setup kernels -------------------
__global__ void k_init_deg(const int* __restrict__ ei32, int E, int n) {
    int i = blockIdx.x * blockDim.x + threadIdx.x;
    if (i < n) g_deg[i] = 0;
    if (blockIdx.x == 0 && threadIdx.x == 0) {
        // dtype sniff: int64 indices < 1e5 have zero odd words
        int all0 = 1;
        int m = (E > 64) ? 64 : E;
        for (int q = 0; q < m; q++)
            if (ei32[2 * q + 1] != 0) { all0 = 0; break; }
        g_is64 = all0;
    }
}

__global__ void k_deg_count(const void* __restrict__ ei, int E, int n) {
    int i = blockIdx.x * blockDim.x + threadIdx.x;
    if (i < E) {
        int s, d;
        if (g_is64) {
            s = (int)((const long long*)ei)[i];
            d = (int)((const long long*)ei)[(size_t)E + i];
        } else {
            s = ((const int*)ei)[i];
            d = ((const int*)ei)[(size_t)E + i];
        }
        s = min(max(s, 0), n - 1);
        d = min(max(d, 0), n - 1);
        g_src[i] = s;
        g_dst[i] = d;
        atomicAdd(&g_deg[d], 1);
    }
}

// pass 1: per-block (1024 elems) sums of deg; also compute dinv.
__global__ void __launch_bounds__(1024) k_scan1(int n) {
    __shared__ int wsum[32];
    int t = threadIdx.x, lane = t & 31, wid = t >> 5;
    int i = blockIdx.x * 1024 + t;
    int v = (i < n) ? g_deg[i] : 0;
    if (i < n) g_dinv[i] = rsqrtf((float)v + 1.0f);
    int x = v;
#pragma unroll
    for (int off = 16; off; off >>= 1) x += __shfl_down_sync(0xffffffffu, x, off);
    if (lane == 0) wsum[wid] = x;
    __syncthreads();
    if (wid == 0) {
        int y = wsum[lane];
#pragma unroll
        for (int off = 16; off; off >>= 1) y += __shfl_down_sync(0xffffffffu, y, off);
        if (lane == 0) g_bsum[blockIdx.x] = y;
    }
}

// pass 2: exclusive scan of block sums (nb <= 256), single block of 256.
__global__ void __launch_bounds__(256) k_scan2(int nb) {
    __shared__ int wsum[8];
    int t = threadIdx.x, lane = t & 31, wid = t >> 5;
    int v = (t < nb) ? g_bsum[t] : 0;
    int x = v;
#pragma unroll
    for (int off = 1; off < 32; off <<= 1) {
        int y = __shfl_up_sync(0xffffffffu, x, off);
        if (lane >= off) x += y;
    }
    if (lane == 31) wsum[wid] = x;
    __syncthreads();
    if (wid == 0 && lane < 8) {
        int w = wsum[lane];
        int xx = w;
#pragma unroll
        for (int off = 1; off < 8; off <<= 1) {
            int y = __shfl_up_sync(0xffu, xx, off);
            if (lane >= off) xx += y;
        }
        wsum[lane] = xx - w;  // exclusive warp offsets
    }
    __syncthreads();
    if (t < nb) g_bsum[t] = wsum[wid] + (x - v);
}

// pass 3: local exclusive scan + block offset -> rowoff, cursor.
__global__ void __launch_bounds__(1024) k_scan3(int n) {
    __shared__ int wsum[32];
    int t = threadIdx.x, lane = t & 31, wid = t >> 5;
    int i = blockIdx.x * 1024 + t;
    int v = (i < n) ? g_deg[i] : 0;
    int x = v;
#pragma unroll
    for (int off = 1; off < 32; off <<= 1) {
        int y = __shfl_up_sync(0xffffffffu, x, off);
        if (lane >= off) x += y;
    }
    if (lane == 31) wsum[wid] = x;
    __syncthreads();
    if (wid == 0) {
        int w = wsum[lane];
        int xx = w;
#pragma unroll
        for (int off = 1; off < 32; off <<= 1) {
            int y = __shfl_up_sync(0xffffffffu, xx, off);
            if (lane >= off) xx += y;
        }
        wsum[lane] = xx - w;
    }
    __syncthreads();
    int excl = g_bsum[blockIdx.x] + wsum[wid] + (x - v);
    if (i < n) {
        g_rowoff[i] = excl;
        g_cursor[i] = excl;
    }
    if (i == n - 1) g_rowoff[n] = excl + v;
}

__global__ void k_fill(int E) {
    int i = blockIdx.x * blockDim.x + threadIdx.x;
    if (i < E) {
        int d = g_dst[i];
        int p = atomicAdd(&g_cursor[d], 1);
        g_csr[p] = g_src[i];
    }
}

// ------------------- pipelined register-tiled GEMM (NO dinv scaling) -------------------
// g_bufA[node, :NP) = X[node,:] @ W  (rows padded to NP).
// Independent of the graph branch -> overlaps with CSR build on a side stream.
template <int NQ, int TY, int TM, int KREAL, int KLOOP, int LDX,
          int NREAL, int NP, bool FROM_PARAM, int MAXB>
__global__ void __launch_bounds__(NQ * TY, MAXB)
k_gemm_pipe(const float* __restrict__ Xp, const float* __restrict__ W, int n) {
    constexpr int KK = 16;
    constexpr int NT = (KLOOP + KK - 1) / KK;
    constexpr int BM = TY * TM;
    constexpr int BMP = BM + 2;
    constexpr int THREADS = NQ * TY;
    __shared__ __align__(16) float2 xs2[2][KK][BMP];
    __shared__ __align__(16) float4 ws4[2][KK][NQ];
    const float* X = FROM_PARAM ? Xp : (const float*)g_bufB;
    const int tx = threadIdx.x, ty = threadIdx.y;
    const int t = ty * NQ + tx;
    const int node0 = blockIdx.x * BM;

    unsigned long long acc[2 * TM];
#pragma unroll
    for (int h = 0; h < 2 * TM; h++) acc[h] = 0ull;

    auto load_tile = [&](int tile, int buf) {
        const int k0 = tile * KK;
        for (int idx = t; idx < BM * KK; idx += THREADS) {
            int nl = idx >> 4;
            int kk = idx & 15;
            int k = k0 + kk;
            int node = node0 + nl;
            float v = 0.0f;
            if (k < LDX && node < n) v = X[(size_t)node * LDX + k];
            xs2[buf][kk][nl] = make_float2(v, v);
        }
        for (int idx = t; idx < KK * NQ; idx += THREADS) {
            int kk = idx / NQ;
            int q = idx - kk * NQ;
            int j = q * 4;
            int gk = k0 + kk;
            float4 w = make_float4(0.f, 0.f, 0.f, 0.f);
            if (gk < KREAL) {
                const float* wr = W + (size_t)gk * NREAL;
                if (j + 0 < NREAL) w.x = wr[j + 0];
                if (j + 1 < NREAL) w.y = wr[j + 1];
                if (j + 2 < NREAL) w.z = wr[j + 2];
                if (j + 3 < NREAL) w.w = wr[j + 3];
            }
            ws4[buf][kk][q] = w;
        }
    };

    load_tile(0, 0);
    __syncthreads();

    for (int tile = 0; tile < NT; tile++) {
        const int cur = tile & 1;
        if (tile + 1 < NT) load_tile(tile + 1, cur ^ 1);
#pragma unroll
        for (int kk = 0; kk < KK; kk++) {
            ulonglong2 w = *reinterpret_cast<const ulonglong2*>(&ws4[cur][kk][tx]);
#pragma unroll
            for (int j = 0; j < TM / 2; j++) {
                ulonglong2 xp = *reinterpret_cast<const ulonglong2*>(
                    &xs2[cur][kk][ty * TM + 2 * j]);
                FMA2(acc[4 * j + 0], xp.x, w.x, acc[4 * j + 0]);
                FMA2(acc[4 * j + 1], xp.x, w.y, acc[4 * j + 1]);
                FMA2(acc[4 * j + 2], xp.y, w.x, acc[4 * j + 2]);
                FMA2(acc[4 * j + 3], xp.y, w.y, acc[4 * j + 3]);
            }
        }
        __syncthreads();
    }

    float4* Y4 = (float4*)g_bufA;
#pragma unroll
    for (int m = 0; m < TM; m++) {
        int node = node0 + ty * TM + m;
        if (node < n) {
            float4 o;
            upk2(o.x, o.y, acc[2 * m]);
            upk2(o.z, o.w, acc[2 * m + 1]);
            Y4[(size_t)node * NQ + tx] = o;
        }
    }
}

// Layer-3 GEMM (N=1): y[node] = h2[node,:] . W3  (no dinv), smem-tiled x.
__global__ void __launch_bounds__(256)
k_gemm_n1(const float* __restrict__ W, int n) {
    constexpr int BM = 256, KK = 32, KLOOP = NP2, KREAL = H2;
    __shared__ float xs[KK][BM + 1];
    __shared__ float ws[KLOOP];
    const float* X = (const float*)g_bufB;
    const int t = threadIdx.x;
    const int node0 = blockIdx.x * BM;
    if (t < KLOOP) ws[t] = (t < KREAL) ? W[t] : 0.0f;
    __syncthreads();
    float acc = 0.0f;
    for (int k0 = 0; k0 < KLOOP; k0 += KK) {
        const int kc = (KLOOP - k0 < KK) ? (KLOOP - k0) : KK;
        for (int idx = t; idx < BM * KK; idx += 256) {
            int nl = idx >> 5;
            int kk = idx & 31;
            int node = node0 + nl;
            float v = 0.0f;
            if (kk < kc && node < n) v = X[(size_t)node * NP2 + k0 + kk];
            xs[kk][nl] = v;
        }
        __syncthreads();
#pragma unroll 8
        for (int kk = 0; kk < kc; kk++) acc += xs[kk][t] * ws[k0 + kk];
        __syncthreads();
    }
    const int node = node0 + t;
    if (node < n) g_bufA[node] = acc;
}

// ------------------- gather: flat mapping, dinv applied here -------------------
// g_bufB[i,:] = dinv[i] * (sum_{s in N(i)} dinv[s]*xw[s,:] + dinv[i]*xw[i,:]) + b
template <int NQ4, int NREAL, bool RELU>
__global__ void __launch_bounds__(256)
k_gather_flat(const float* __restrict__ b, int n) {
    const int gt = blockIdx.x * blockDim.x + threadIdx.x;
    const int node = gt / NQ4;
    const int lane = gt - node * NQ4;
    if (node >= n) return;
    const float4* __restrict__ xw = (const float4*)g_bufA;

    float4 a0 = make_float4(0.f, 0.f, 0.f, 0.f);
    float4 a1 = make_float4(0.f, 0.f, 0.f, 0.f);
    float4 a2 = make_float4(0.f, 0.f, 0.f, 0.f);
    float4 a3 = make_float4(0.f, 0.f, 0.f, 0.f);

    const int beg = g_rowoff[node];
    const int end = g_rowoff[node + 1];
    int e = beg;
    for (; e + 3 < end; e += 4) {
        int s0 = g_csr[e];
        int s1 = g_csr[e + 1];
        int s2 = g_csr[e + 2];
        int s3 = g_csr[e + 3];
        float w0 = __ldg(&g_dinv[s0]);
        float w1 = __ldg(&g_dinv[s1]);
        float w2 = __ldg(&g_dinv[s2]);
        float w3 = __ldg(&g_dinv[s3]);
        float4 v0 = __ldg(&xw[(size_t)s0 * NQ4 + lane]);
        float4 v1 = __ldg(&xw[(size_t)s1 * NQ4 + lane]);
        float4 v2 = __ldg(&xw[(size_t)s2 * NQ4 + lane]);
        float4 v3 = __ldg(&xw[(size_t)s3 * NQ4 + lane]);
        a0.x = fmaf(w0, v0.x, a0.x); a0.y = fmaf(w0, v0.y, a0.y);
        a0.z = fmaf(w0, v0.z, a0.z); a0.w = fmaf(w0, v0.w, a0.w);
        a1.x = fmaf(w1, v1.x, a1.x); a1.y = fmaf(w1, v1.y, a1.y);
        a1.z = fmaf(w1, v1.z, a1.z); a1.w = fmaf(w1, v1.w, a1.w);
        a2.x = fmaf(w2, v2.x, a2.x); a2.y = fmaf(w2, v2.y, a2.y);
        a2.z = fmaf(w2, v2.z, a2.z); a2.w = fmaf(w2, v2.w, a2.w);
        a3.x = fmaf(w3, v3.x, a3.x); a3.y = fmaf(w3, v3.y, a3.y);
        a3.z = fmaf(w3, v3.z, a3.z); a3.w = fmaf(w3, v3.w, a3.w);
    }
    for (; e < end; e++) {
        int s0 = g_csr[e];
        float w0 = __ldg(&g_dinv[s0]);
        float4 v0 = __ldg(&xw[(size_t)s0 * NQ4 + lane]);
        a0.x = fmaf(w0, v0.x, a0.x); a0.y = fmaf(w0, v0.y, a0.y);
        a0.z = fmaf(w0, v0.z, a0.z); a0.w = fmaf(w0, v0.w, a0.w);
    }
    const float di = g_dinv[node];
    float4 yi = __ldg(&xw[(size_t)node * NQ4 + lane]);
    a0.x += a1.x + a2.x + a3.x + di * yi.x;
    a0.y += a1.y + a2.y + a3.y + di * yi.y;
    a0.z += a1.z + a2.z + a3.z + di * yi.z;
    a0.w += a1.w + a2.w + a3.w + di * yi.w;
    const int c = lane * 4;
    float4 bv = make_float4(0.f, 0.f, 0.f, 0.f);
    if (c + 0 < NREAL) bv.x = __ldg(&b[c + 0]);
    if (c + 1 < NREAL) bv.y = __ldg(&b[c + 1]);
    if (c + 2 < NREAL) bv.z = __ldg(&b[c + 2]);
    if (c + 3 < NREAL) bv.w = __ldg(&b[c + 3]);
    float4 v;
    v.x = fmaf(di, a0.x, bv.x);
    v.y = fmaf(di, a0.y, bv.y);
    v.z = fmaf(di, a0.z, bv.z);
    v.w = fmaf(di, a0.w, bv.w);
    if (RELU) {
        v.x = fmaxf(v.x, 0.f); v.y = fmaxf(v.y, 0.f);
        v.z = fmaxf(v.z, 0.f); v.w = fmaxf(v.w, 0.f);
    }
    // pad cols stay zero (keeps next layer's pad-K columns inert)
    if (c + 0 >= NREAL) v.x = 0.f;
    if (c + 1 >= NREAL) v.y = 0.f;
    if (c + 2 >= NREAL) v.z = 0.f;
    if (c + 3 >= NREAL) v.w = 0.f;
    ((float4*)g_bufB)[(size_t)node * NQ4 + lane] = v;
}

// Final layer (scalar): lanes over edges, shfl reduce; writes d_out.
__global__ void __launch_bounds__(256)
k_gather_out(const float* __restrict__ b, float* __restrict__ out, int n) {
    const int node = (blockIdx.x * blockDim.x + threadIdx.x) >> 5;
    if (node >= n) return;
    const int lane = threadIdx.x & 31;
    const float* y = (const float*)g_bufA;  // stride 1, UNscaled
    const int beg = g_rowoff[node];
    const int end = g_rowoff[node + 1];
    float acc = 0.0f;
    for (int e = beg + lane; e < end; e += 32) {
        int s = g_csr[e];
        acc = fmaf(__ldg(&g_dinv[s]), __ldg(&y[s]), acc);
    }
#pragma unroll
    for (int off = 16; off; off >>= 1) acc += __shfl_down_sync(0xffffffffu, acc, off);
    if (lane == 0) {
        float di = g_dinv[node];
        out[node] = di * (acc + di * y[node]) + __ldg(&b[0]);
    }
}

// ------------------- launcher: fork CSR build || layer-1 GEMM -------------------
extern "C" void kernel_launch(void* const* d_in, const int* in_sizes, int n_in,
                              void* d_out, int out_size) {
    const float* x   = (const float*)d_in[0];
    const void*  ei  = d_in[1];
    const float* W1  = (const float*)d_in[2];
    const float* b1  = (const float*)d_in[3];
    const float* W2  = (const float*)d_in[4];
    const float* b2  = (const float*)d_in[5];
    const float* W3  = (const float*)d_in[6];
    const float* b3  = (const float*)d_in[7];
    float*       out = (float*)d_out;

    const int n = in_sizes[0] / IN_C;
    const int E = in_sizes[1] / 2;

    const int TB = 256;
    const int nb_nodes = (n + TB - 1) / TB;
    const int nb_edges = (E + TB - 1) / TB;
    const int nb_warps = (n * 32 + TB - 1) / TB;
    const int nb_scan  = (n + 1023) / 1024;
    const int nb_n1    = (n + 255) / 256;
    const int nb_gemm1 = (n + 111) / 112;  // NQ=18 x TY=14, TM=8 -> BM=112
    const int nb_gemm2 = (n + 95) / 96;    // NQ=21 x TY=12, TM=8 -> BM=96
    const int nb_gath1 = ((long long)n * (NP1 / 4) + TB - 1) / TB;
    const int nb_gath2 = ((long long)n * (NP2 / 4) + TB - 1) / TB;

    // One-time side stream + events (created on the uncaptured correctness call;
    // reused identically on every call -> deterministic captured graph).
    static cudaStream_t sB = nullptr;
    static cudaEvent_t evFork = nullptr, evJoin = nullptr;
    if (sB == nullptr) {
        cudaStreamCreateWithFlags(&sB, cudaStreamNonBlocking);
        cudaEventCreateWithFlags(&evFork, cudaEventDisableTiming);
        cudaEventCreateWithFlags(&evJoin, cudaEventDisableTiming);
    }

    // main: init (zeros deg, sniffs dtype)
    k_init_deg<<<nb_nodes, TB>>>((const int*)ei, E, n);
    cudaEventRecord(evFork, 0);
    cudaStreamWaitEvent(sB, evFork, 0);

    // side stream: CSR build (deg count, scan, fill)
    k_deg_count<<<nb_edges, TB, 0, sB>>>(ei, E, n);
    k_scan1<<<nb_scan, 1024, 0, sB>>>(n);
    k_scan2<<<1, 256, 0, sB>>>(nb_scan);
    k_scan3<<<nb_scan, 1024, 0, sB>>>(n);
    k_fill<<<nb_edges, TB, 0, sB>>>(E);
    cudaEventRecord(evJoin, sB);

    // main: layer-1 GEMM runs CONCURRENTLY with the CSR build
    k_gemm_pipe<18, 14, 8, IN_C, IN_C, IN_C, H1, NP1, true, 3>
        <<<nb_gemm1, dim3(18, 14)>>>(x, W1, n);

    // join: gathers need both CSR and gemm output
    cudaStreamWaitEvent(0, evJoin, 0);

    // Layer 1 gather: bufA -> bufB [stride 72]
    k_gather_flat<NP1 / 4, H1, true><<<nb_gath1, TB>>>(b1, n);

    // Layer 2 GEMM + gather [stride 84]
    k_gemm_pipe<21, 12, 8, H1, NP1, NP1, H2, NP2, false, 3>
        <<<nb_gemm2, dim3(21, 12)>>>(nullptr, W2, n);
    k_gather_flat<NP2 / 4, H2, false><<<nb_gath2, TB>>>(b2, n);

    // Layer 3: y = h2@W3 [stride 1] ; gather+bias -> out
    k_gemm_n1<<<nb_n1, 256>>>(W3, n);
    k_gather_out<<<nb_warps, TB>>>(b3, out, n);
}

// round 12
// speedup vs baseline: 1.5159x; 1.4500x over previous
#include <cuda_runtime.h>
#include <cuda_bf16.h>
#include <math.h>

// Problem constants (from reference)
#define N_NODES_MAX 100000
#define E_MAX       1600000
#define IN_C 128
#define H1   71
#define H2   82
// padded row strides (floats)
#define NP1  72   // H1 padded  (18 quads)
#define NP2  84   // (buffer sizing only)

// ------------------- device scratch (static, no allocation) -------------------
__device__ int   g_is64;
__device__ int   g_deg[N_NODES_MAX];
__device__ float g_dinv[N_NODES_MAX];
__device__ int   g_rowoff[N_NODES_MAX + 1];
__device__ int   g_cursor[N_NODES_MAX];
__device__ int   g_csr[E_MAX];
__device__ int   g_src[E_MAX];
__device__ int   g_dst[E_MAX];
__device__ int   g_bsum[256];
__device__ float g_w23[NP1];   // W2 @ W3 (padded)
__device__ float g_beta;       // b2 . W3
__device__ float g_bufA[(size_t)N_NODES_MAX * NP2];  // gemm1 out / v
__device__ float g_bufB[(size_t)N_NODES_MAX * NP2];  // h1 / t

// ------------------- packed f32x2 helpers -------------------
__device__ __forceinline__ void upk2(float& lo, float& hi, unsigned long long v) {
    asm("mov.b64 {%0, %1}, %2;" : "=f"(lo), "=f"(hi) : "l"(v));
}
#define FMA2(d, a, b, c) \
    asm("fma.rn.f32x2 %0, %1, %2, %3;" : "=l"(d) : "l"(a), "l"(b), "l"(c))

// ------------------- setup kernels -------------------
__global__ void k_init_deg(const int* __restrict__ ei32, int E, int n) {
    int i = blockIdx.x * blockDim.x + threadIdx.x;
    if (i < n) g_deg[i] = 0;
    if (blockIdx.x == 0 && threadIdx.x == 0) {
        // dtype sniff: int64 indices < 1e5 have zero odd words
        int all0 = 1;
        int m = (E > 64) ? 64 : E;
        for (int q = 0; q < m; q++)
            if (ei32[2 * q + 1] != 0) { all0 = 0; break; }
        g_is64 = all0;
    }
}

__global__ void k_deg_count(const void* __restrict__ ei, int E, int n) {
    int i = blockIdx.x * blockDim.x + threadIdx.x;
    if (i < E) {
        int s, d;
        if (g_is64) {
            s = (int)((const long long*)ei)[i];
            d = (int)((const long long*)ei)[(size_t)E + i];
        } else {
            s = ((const int*)ei)[i];
            d = ((const int*)ei)[(size_t)E + i];
        }
        s = min(max(s, 0), n - 1);
        d = min(max(d, 0), n - 1);
        g_src[i] = s;
        g_dst[i] = d;
        atomicAdd(&g_deg[d], 1);
    }
}

__global__ void __launch_bounds__(1024) k_scan1(int n) {
    __shared__ int wsum[32];
    int t = threadIdx.x, lane = t & 31, wid = t >> 5;
    int i = blockIdx.x * 1024 + t;
    int v = (i < n) ? g_deg[i] : 0;
    if (i < n) g_dinv[i] = rsqrtf((float)v + 1.0f);
    int x = v;
#pragma unroll
    for (int off = 16; off; off >>= 1) x += __shfl_down_sync(0xffffffffu, x, off);
    if (lane == 0) wsum[wid] = x;
    __syncthreads();
    if (wid == 0) {
        int y = wsum[lane];
#pragma unroll
        for (int off = 16; off; off >>= 1) y += __shfl_down_sync(0xffffffffu, y, off);
        if (lane == 0) g_bsum[blockIdx.x] = y;
    }
}

__global__ void __launch_bounds__(256) k_scan2(int nb) {
    __shared__ int wsum[8];
    int t = threadIdx.x, lane = t & 31, wid = t >> 5;
    int v = (t < nb) ? g_bsum[t] : 0;
    int x = v;
#pragma unroll
    for (int off = 1; off < 32; off <<= 1) {
        int y = __shfl_up_sync(0xffffffffu, x, off);
        if (lane >= off) x += y;
    }
    if (lane == 31) wsum[wid] = x;
    __syncthreads();
    if (wid == 0 && lane < 8) {
        int w = wsum[lane];
        int xx = w;
#pragma unroll
        for (int off = 1; off < 8; off <<= 1) {
            int y = __shfl_up_sync(0xffu, xx, off);
            if (lane >= off) xx += y;
        }
        wsum[lane] = xx - w;
    }
    __syncthreads();
    if (t < nb) g_bsum[t] = wsum[wid] + (x - v);
}

__global__ void __launch_bounds__(1024) k_scan3(int n) {
    __shared__ int wsum[32];
    int t = threadIdx.x, lane = t & 31, wid = t >> 5;
    int i = blockIdx.x * 1024 + t;
    int v = (i < n) ? g_deg[i] : 0;
    int x = v;
#pragma unroll
    for (int off = 1; off < 32; off <<= 1) {
        int y = __shfl_up_sync(0xffffffffu, x, off);
        if (lane >= off) x += y;
    }
    if (lane == 31) wsum[wid] = x;
    __syncthreads();
    if (wid == 0) {
        int w = wsum[lane];
        int xx = w;
#pragma unroll
        for (int off = 1; off < 32; off <<= 1) {
            int y = __shfl_up_sync(0xffffffffu, xx, off);
            if (lane >= off) xx += y;
        }
        wsum[lane] = xx - w;
    }
    __syncthreads();
    int excl = g_bsum[blockIdx.x] + wsum[wid] + (x - v);
    if (i < n) {
        g_rowoff[i] = excl;
        g_cursor[i] = excl;
    }
    if (i == n - 1) g_rowoff[n] = excl + v;
}

__global__ void k_fill(int E) {
    int i = blockIdx.x * blockDim.x + threadIdx.x;
    if (i < E) {
        int d = g_dst[i];
        int p = atomicAdd(&g_cursor[d], 1);
        g_csr[p] = g_src[i];
    }
}

// ------------------- layer 2+3 collapse: w23 = W2 @ W3, beta = b2 . W3 -----------
__global__ void k_w23(const float* __restrict__ W2, const float* __restrict__ W3,
                      const float* __restrict__ b2) {
    __shared__ float w3s[H2];
    int t = threadIdx.x;
    if (t < H2) w3s[t] = W3[t];
    __syncthreads();
    if (t < NP1) {
        float s = 0.0f;
        if (t < H1) {
            const float* r = W2 + (size_t)t * H2;
#pragma unroll 2
            for (int j = 0; j < H2; j++) s = fmaf(r[j], w3s[j], s);
        }
        g_w23[t] = s;
    }
    if (t == 127) {
        float be = 0.0f;
        for (int j = 0; j < H2; j++) be = fmaf(b2[j], w3s[j], be);
        g_beta = be;
    }
}

// ------------------- pipelined register-tiled GEMM (layer 1, UNscaled) -----------
// g_bufA[node, :NP) = X[node,:] @ W. Independent of graph branch (fork-overlapped).
template <int NQ, int TY, int TM, int KREAL, int KLOOP, int LDX,
          int NREAL, int NP, int MAXB>
__global__ void __launch_bounds__(NQ * TY, MAXB)
k_gemm_pipe(const float* __restrict__ X, const float* __restrict__ W, int n) {
    constexpr int KK = 16;
    constexpr int NT = (KLOOP + KK - 1) / KK;
    constexpr int BM = TY * TM;
    constexpr int BMP = BM + 2;
    constexpr int THREADS = NQ * TY;
    __shared__ __align__(16) float2 xs2[2][KK][BMP];
    __shared__ __align__(16) float4 ws4[2][KK][NQ];
    const int tx = threadIdx.x, ty = threadIdx.y;
    const int t = ty * NQ + tx;
    const int node0 = blockIdx.x * BM;

    unsigned long long acc[2 * TM];
#pragma unroll
    for (int h = 0; h < 2 * TM; h++) acc[h] = 0ull;

    auto load_tile = [&](int tile, int buf) {
        const int k0 = tile * KK;
        // x tile: float4 global loads (KLOOP exact multiple of KK, LDX mult of 4)
        for (int idx = t; idx < BM * (KK / 4); idx += THREADS) {
            int nl = idx >> 2;          // KK/4 == 4
            int kq = idx & 3;
            int node = node0 + nl;
            float4 v = make_float4(0.f, 0.f, 0.f, 0.f);
            if (node < n)
                v = *(const float4*)(X + (size_t)node * LDX + k0 + kq * 4);
            xs2[buf][kq * 4 + 0][nl] = make_float2(v.x, v.x);
            xs2[buf][kq * 4 + 1][nl] = make_float2(v.y, v.y);
            xs2[buf][kq * 4 + 2][nl] = make_float2(v.z, v.z);
            xs2[buf][kq * 4 + 3][nl] = make_float2(v.w, v.w);
        }
        // W chunk, zero-padded in k and N
        for (int idx = t; idx < KK * NQ; idx += THREADS) {
            int kk = idx / NQ;
            int q = idx - kk * NQ;
            int j = q * 4;
            int gk = k0 + kk;
            float4 w = make_float4(0.f, 0.f, 0.f, 0.f);
            if (gk < KREAL) {
                const float* wr = W + (size_t)gk * NREAL;
                if (j + 0 < NREAL) w.x = wr[j + 0];
                if (j + 1 < NREAL) w.y = wr[j + 1];
                if (j + 2 < NREAL) w.z = wr[j + 2];
                if (j + 3 < NREAL) w.w = wr[j + 3];
            }
            ws4[buf][kk][q] = w;
        }
    };

    load_tile(0, 0);
    __syncthreads();

    for (int tile = 0; tile < NT; tile++) {
        const int cur = tile & 1;
        if (tile + 1 < NT) load_tile(tile + 1, cur ^ 1);
#pragma unroll
        for (int kk = 0; kk < KK; kk++) {
            ulonglong2 w = *reinterpret_cast<const ulonglong2*>(&ws4[cur][kk][tx]);
#pragma unroll
            for (int j = 0; j < TM / 2; j++) {
                ulonglong2 xp = *reinterpret_cast<const ulonglong2*>(
                    &xs2[cur][kk][ty * TM + 2 * j]);
                FMA2(acc[4 * j + 0], xp.x, w.x, acc[4 * j + 0]);
                FMA2(acc[4 * j + 1], xp.x, w.y, acc[4 * j + 1]);
                FMA2(acc[4 * j + 2], xp.y, w.x, acc[4 * j + 2]);
                FMA2(acc[4 * j + 3], xp.y, w.y, acc[4 * j + 3]);
            }
        }
        __syncthreads();
    }

    float4* Y4 = (float4*)g_bufA;
#pragma unroll
    for (int m = 0; m < TM; m++) {
        int node = node0 + ty * TM + m;
        if (node < n) {
            float4 o;
            upk2(o.x, o.y, acc[2 * m]);
            upk2(o.z, o.w, acc[2 * m + 1]);
            Y4[(size_t)node * NQ + tx] = o;
        }
    }
}

// ------------------- gather layer 1: flat mapping, dinv applied here -------------
// g_bufB[i,:] = relu( dinv_i*(sum_s dinv_s*xw[s,:] + dinv_i*xw[i,:]) + b )
template <int NQ4, int NREAL, bool RELU>
__global__ void __launch_bounds__(256)
k_gather_flat(const float* __restrict__ b, int n) {
    const int gt = blockIdx.x * blockDim.x + threadIdx.x;
    const int node = gt / NQ4;
    const int lane = gt - node * NQ4;
    if (node >= n) return;
    const float4* __restrict__ xw = (const float4*)g_bufA;

    float4 a0 = make_float4(0.f, 0.f, 0.f, 0.f);
    float4 a1 = make_float4(0.f, 0.f, 0.f, 0.f);
    float4 a2 = make_float4(0.f, 0.f, 0.f, 0.f);
    float4 a3 = make_float4(0.f, 0.f, 0.f, 0.f);

    const int beg = g_rowoff[node];
    const int end = g_rowoff[node + 1];
    int e = beg;
    for (; e + 3 < end; e += 4) {
        int s0 = g_csr[e];
        int s1 = g_csr[e + 1];
        int s2 = g_csr[e + 2];
        int s3 = g_csr[e + 3];
        float w0 = __ldg(&g_dinv[s0]);
        float w1 = __ldg(&g_dinv[s1]);
        float w2 = __ldg(&g_dinv[s2]);
        float w3 = __ldg(&g_dinv[s3]);
        float4 v0 = __ldg(&xw[(size_t)s0 * NQ4 + lane]);
        float4 v1 = __ldg(&xw[(size_t)s1 * NQ4 + lane]);
        float4 v2 = __ldg(&xw[(size_t)s2 * NQ4 + lane]);
        float4 v3 = __ldg(&xw[(size_t)s3 * NQ4 + lane]);
        a0.x = fmaf(w0, v0.x, a0.x); a0.y = fmaf(w0, v0.y, a0.y);
        a0.z = fmaf(w0, v0.z, a0.z); a0.w = fmaf(w0, v0.w, a0.w);
        a1.x = fmaf(w1, v1.x, a1.x); a1.y = fmaf(w1, v1.y, a1.y);
        a1.z = fmaf(w1, v1.z, a1.z); a1.w = fmaf(w1, v1.w, a1.w);
        a2.x = fmaf(w2, v2.x, a2.x); a2.y = fmaf(w2, v2.y, a2.y);
        a2.z = fmaf(w2, v2.z, a2.z); a2.w = fmaf(w2, v2.w, a2.w);
        a3.x = fmaf(w3, v3.x, a3.x); a3.y = fmaf(w3, v3.y, a3.y);
        a3.z = fmaf(w3, v3.z, a3.z); a3.w = fmaf(w3, v3.w, a3.w);
    }
    for (; e < end; e++) {
        int s0 = g_csr[e];
        float w0 = __ldg(&g_dinv[s0]);
        float4 v0 = __ldg(&xw[(size_t)s0 * NQ4 + lane]);
        a0.x = fmaf(w0, v0.x, a0.x); a0.y = fmaf(w0, v0.y, a0.y);
        a0.z = fmaf(w0, v0.z, a0.z); a0.w = fmaf(w0, v0.w, a0.w);
    }
    const float di = g_dinv[node];
    float4 yi = __ldg(&xw[(size_t)node * NQ4 + lane]);
    a0.x += a1.x + a2.x + a3.x + di * yi.x;
    a0.y += a1.y + a2.y + a3.y + di * yi.y;
    a0.z += a1.z + a2.z + a3.z + di * yi.z;
    a0.w += a1.w + a2.w + a3.w + di * yi.w;
    const int c = lane * 4;
    float4 bv = make_float4(0.f, 0.f, 0.f, 0.f);
    if (c + 0 < NREAL) bv.x = __ldg(&b[c + 0]);
    if (c + 1 < NREAL) bv.y = __ldg(&b[c + 1]);
    if (c + 2 < NREAL) bv.z = __ldg(&b[c + 2]);
    if (c + 3 < NREAL) bv.w = __ldg(&b[c + 3]);
    float4 v;
    v.x = fmaf(di, a0.x, bv.x);
    v.y = fmaf(di, a0.y, bv.y);
    v.z = fmaf(di, a0.z, bv.z);
    v.w = fmaf(di, a0.w, bv.w);
    if (RELU) {
        v.x = fmaxf(v.x, 0.f); v.y = fmaxf(v.y, 0.f);
        v.z = fmaxf(v.z, 0.f); v.w = fmaxf(v.w, 0.f);
    }
    if (c + 0 >= NREAL) v.x = 0.f;
    if (c + 1 >= NREAL) v.y = 0.f;
    if (c + 2 >= NREAL) v.z = 0.f;
    if (c + 3 >= NREAL) v.w = 0.f;
    ((float4*)g_bufB)[(size_t)node * NQ4 + lane] = v;
}

// ------------------- GEMV: v[node] = h1[node,:] . w23  (bufB -> bufA) ------------
__global__ void __launch_bounds__(256)
k_gemv(int n) {
    constexpr int BM = 256, KK = 24, KLOOP = NP1;
    __shared__ float xs[KK][BM + 1];
    __shared__ float ws[KLOOP];
    const float* X = (const float*)g_bufB;
    const int t = threadIdx.x;
    const int node0 = blockIdx.x * BM;
    if (t < KLOOP) ws[t] = g_w23[t];
    __syncthreads();
    float acc = 0.0f;
    for (int k0 = 0; k0 < KLOOP; k0 += KK) {
        for (int idx = t; idx < BM * KK; idx += 256) {
            int nl = idx / KK;
            int kk = idx - nl * KK;
            int node = node0 + nl;
            xs[kk][nl] = (node < n) ? X[(size_t)node * NP1 + k0 + kk] : 0.0f;
        }
        __syncthreads();
#pragma unroll
        for (int kk = 0; kk < KK; kk++) acc = fmaf(xs[kk][t], ws[k0 + kk], acc);
        __syncthreads();
    }
    const int node = node0 + t;
    if (node < n) g_bufA[node] = acc;
}

// ------------------- scalar gather (two phases) -----------------------------------
// PHASE 0: t = Anorm . v + beta      (g_bufA -> g_bufB)
// PHASE 1: out = Anorm . t + b[0]    (g_bufB -> out)
template <int PHASE>
__global__ void __launch_bounds__(256)
k_gather_scalar(const float* __restrict__ b, float* __restrict__ out, int n) {
    const int node = (blockIdx.x * blockDim.x + threadIdx.x) >> 5;
    if (node >= n) return;
    const int lane = threadIdx.x & 31;
    const float* y = (PHASE == 0) ? (const float*)g_bufA : (const float*)g_bufB;
    const int beg = g_rowoff[node];
    const int end = g_rowoff[node + 1];
    float acc = 0.0f;
    for (int e = beg + lane; e < end; e += 32) {
        int s = g_csr[e];
        acc = fmaf(__ldg(&g_dinv[s]), __ldg(&y[s]), acc);
    }
#pragma unroll
    for (int off = 16; off; off >>= 1) acc += __shfl_down_sync(0xffffffffu, acc, off);
    if (lane == 0) {
        float di = g_dinv[node];
        float bias = (PHASE == 0) ? g_beta : __ldg(&b[0]);
        float r = di * (acc + di * y[node]) + bias;
        if (PHASE == 0) ((float*)g_bufB)[node] = r;
        else out[node] = r;
    }
}

// ------------------- launcher: fork CSR build || layer-1 GEMM ---------------------
extern "C" void kernel_launch(void* const* d_in, const int* in_sizes, int n_in,
                              void* d_out, int out_size) {
    const float* x   = (const float*)d_in[0];
    const void*  ei  = d_in[1];
    const float* W1  = (const float*)d_in[2];
    const float* b1  = (const float*)d_in[3];
    const float* W2  = (const float*)d_in[4];
    const float* b2  = (const float*)d_in[5];
    const float* W3  = (const float*)d_in[6];
    const float* b3  = (const float*)d_in[7];
    float*       out = (float*)d_out;

    const int n = in_sizes[0] / IN_C;
    const int E = in_sizes[1] / 2;

    const int TB = 256;
    const int nb_nodes = (n + TB - 1) / TB;
    const int nb_edges = (E + TB - 1) / TB;
    const int nb_warps = (n * 32 + TB - 1) / TB;
    const int nb_scan  = (n + 1023) / 1024;
    const int nb_gemm1 = (n + 111) / 112;  // NQ=18 x TY=14, TM=8 -> BM=112
    const int nb_gemv  = (n + 255) / 256;
    const int nb_gath1 = ((long long)n * (NP1 / 4) + TB - 1) / TB;

    // One-time side stream + events (created on the uncaptured correctness call;
    // reused identically on every call -> deterministic captured graph).
    static cudaStream_t sB = nullptr;
    static cudaEvent_t evFork = nullptr, evJoin = nullptr;
    if (sB == nullptr) {
        cudaStreamCreateWithFlags(&sB, cudaStreamNonBlocking);
        cudaEventCreateWithFlags(&evFork, cudaEventDisableTiming);
        cudaEventCreateWithFlags(&evJoin, cudaEventDisableTiming);
    }

    // main: init (zeros deg, sniffs dtype)
    k_init_deg<<<nb_nodes, TB>>>((const int*)ei, E, n);           // 0
    cudaEventRecord(evFork, 0);
    cudaStreamWaitEvent(sB, evFork, 0);

    // side stream: CSR build part 1
    k_deg_count<<<nb_edges, TB, 0, sB>>>(ei, E, n);               // 1
    k_scan1<<<nb_scan, 1024, 0, sB>>>(n);                         // 2

    // main: layer-1 GEMM runs CONCURRENTLY with the CSR build
    k_gemm_pipe<18, 14, 8, IN_C, IN_C, IN_C, H1, NP1, 3>
        <<<nb_gemm1, dim3(18, 14)>>>(x, W1, n);                   // 3 <- profiled
    k_w23<<<1, 128>>>(W2, W3, b2);                                // 4 (main)

    // side stream: CSR build part 2
    k_scan2<<<1, 256, 0, sB>>>(nb_scan);                          // 5
    k_scan3<<<nb_scan, 1024, 0, sB>>>(n);                         // 6
    k_fill<<<nb_edges, TB, 0, sB>>>(E);                           // 7
    cudaEventRecord(evJoin, sB);

    // join: gathers need both CSR and gemm output
    cudaStreamWaitEvent(0, evJoin, 0);

    // Layer 1 gather (+bias+relu): bufA -> bufB [stride 72]
    k_gather_flat<NP1 / 4, H1, true><<<nb_gath1, TB>>>(b1, n);

    // Collapsed layers 2+3:
    k_gemv<<<nb_gemv, 256>>>(n);                       // v = h1 . w23  -> bufA
    k_gather_scalar<0><<<nb_warps, TB>>>(nullptr, nullptr, n);  // t -> bufB
    k_gather_scalar<1><<<nb_warps, TB>>>(b3, out, n);           // out
}

// round 13
// speedup vs baseline: 1.6385x; 1.0809x over previous
#include <cuda_runtime.h>
#include <cuda_fp16.h>
#include <math.h>

// Problem constants (from reference)
#define N_NODES_MAX 100000
#define E_MAX       1600000
#define IN_C 128
#define H1   71
#define H2   82
// padded row strides
#define NP1  72   // H1 padded (18 quads / 9 half-uint4 chunks)
#define NP2  84   // (buffer sizing only)

// ------------------- device scratch (static, no allocation) -------------------
__device__ int   g_is64;
__device__ int   g_deg[N_NODES_MAX];
__device__ float g_dinv[N_NODES_MAX];
__device__ int   g_rowoff[N_NODES_MAX + 1];
__device__ int   g_cursor[N_NODES_MAX];
__device__ int   g_csr[E_MAX];
__device__ int   g_src[E_MAX];
__device__ int   g_dst[E_MAX];
__device__ int   g_bsum[256];
__device__ float g_w23[NP1];   // W2 @ W3 (padded)
__device__ float g_beta;       // b2 . W3
__device__ __align__(16) __half g_bufH[(size_t)N_NODES_MAX * NP1];  // xw rows (fp16)
__device__ float g_bufA[(size_t)N_NODES_MAX * NP2];  // v / scratch
__device__ float g_bufB[(size_t)N_NODES_MAX * NP2];  // h1 (fp32) / t

// ------------------- packed f32x2 helpers -------------------
__device__ __forceinline__ void upk2(float& lo, float& hi, unsigned long long v) {
    asm("mov.b64 {%0, %1}, %2;" : "=f"(lo), "=f"(hi) : "l"(v));
}
#define FMA2(d, a, b, c) \
    asm("fma.rn.f32x2 %0, %1, %2, %3;" : "=l"(d) : "l"(a), "l"(b), "l"(c))

// ------------------- setup kernels -------------------
__global__ void k_init_deg(const int* __restrict__ ei32, int E, int n) {
    int i = blockIdx.x * blockDim.x + threadIdx.x;
    if (i < n) g_deg[i] = 0;
    if (blockIdx.x == 0 && threadIdx.x == 0) {
        // dtype sniff: int64 indices < 1e5 have zero odd words
        int all0 = 1;
        int m = (E > 64) ? 64 : E;
        for (int q = 0; q < m; q++)
            if (ei32[2 * q + 1] != 0) { all0 = 0; break; }
        g_is64 = all0;
    }
}

__global__ void k_deg_count(const void* __restrict__ ei, int E, int n) {
    int i = blockIdx.x * blockDim.x + threadIdx.x;
    if (i < E) {
        int s, d;
        if (g_is64) {
            s = (int)((const long long*)ei)[i];
            d = (int)((const long long*)ei)[(size_t)E + i];
        } else {
            s = ((const int*)ei)[i];
            d = ((const int*)ei)[(size_t)E + i];
        }
        s = min(max(s, 0), n - 1);
        d = min(max(d, 0), n - 1);
        g_src[i] = s;
        g_dst[i] = d;
        atomicAdd(&g_deg[d], 1);
    }
}

__global__ void __launch_bounds__(1024) k_scan1(int n) {
    __shared__ int wsum[32];
    int t = threadIdx.x, lane = t & 31, wid = t >> 5;
    int i = blockIdx.x * 1024 + t;
    int v = (i < n) ? g_deg[i] : 0;
    if (i < n) g_dinv[i] = rsqrtf((float)v + 1.0f);
    int x = v;
#pragma unroll
    for (int off = 16; off; off >>= 1) x += __shfl_down_sync(0xffffffffu, x, off);
    if (lane == 0) wsum[wid] = x;
    __syncthreads();
    if (wid == 0) {
        int y = wsum[lane];
#pragma unroll
        for (int off = 16; off; off >>= 1) y += __shfl_down_sync(0xffffffffu, y, off);
        if (lane == 0) g_bsum[blockIdx.x] = y;
    }
}

__global__ void __launch_bounds__(256) k_scan2(int nb) {
    __shared__ int wsum[8];
    int t = threadIdx.x, lane = t & 31, wid = t >> 5;
    int v = (t < nb) ? g_bsum[t] : 0;
    int x = v;
#pragma unroll
    for (int off = 1; off < 32; off <<= 1) {
        int y = __shfl_up_sync(0xffffffffu, x, off);
        if (lane >= off) x += y;
    }
    if (lane == 31) wsum[wid] = x;
    __syncthreads();
    if (wid == 0 && lane < 8) {
        int w = wsum[lane];
        int xx = w;
#pragma unroll
        for (int off = 1; off < 8; off <<= 1) {
            int y = __shfl_up_sync(0xffu, xx, off);
            if (lane >= off) xx += y;
        }
        wsum[lane] = xx - w;
    }
    __syncthreads();
    if (t < nb) g_bsum[t] = wsum[wid] + (x - v);
}

__global__ void __launch_bounds__(1024) k_scan3(int n) {
    __shared__ int wsum[32];
    int t = threadIdx.x, lane = t & 31, wid = t >> 5;
    int i = blockIdx.x * 1024 + t;
    int v = (i < n) ? g_deg[i] : 0;
    int x = v;
#pragma unroll
    for (int off = 1; off < 32; off <<= 1) {
        int y = __shfl_up_sync(0xffffffffu, x, off);
        if (lane >= off) x += y;
    }
    if (lane == 31) wsum[wid] = x;
    __syncthreads();
    if (wid == 0) {
        int w = wsum[lane];
        int xx = w;
#pragma unroll
        for (int off = 1; off < 32; off <<= 1) {
            int y = __shfl_up_sync(0xffffffffu, xx, off);
            if (lane >= off) xx += y;
        }
        wsum[lane] = xx - w;
    }
    __syncthreads();
    int excl = g_bsum[blockIdx.x] + wsum[wid] + (x - v);
    if (i < n) {
        g_rowoff[i] = excl;
        g_cursor[i] = excl;
    }
    if (i == n - 1) g_rowoff[n] = excl + v;
}

__global__ void k_fill(int E) {
    int i = blockIdx.x * blockDim.x + threadIdx.x;
    if (i < E) {
        int d = g_dst[i];
        int p = atomicAdd(&g_cursor[d], 1);
        g_csr[p] = g_src[i];
    }
}

// ------------------- layer 2+3 collapse: w23 = W2 @ W3, beta = b2 . W3 -----------
__global__ void k_w23(const float* __restrict__ W2, const float* __restrict__ W3,
                      const float* __restrict__ b2) {
    __shared__ float w3s[H2];
    int t = threadIdx.x;
    if (t < H2) w3s[t] = W3[t];
    __syncthreads();
    if (t < NP1) {
        float s = 0.0f;
        if (t < H1) {
            const float* r = W2 + (size_t)t * H2;
#pragma unroll 2
            for (int j = 0; j < H2; j++) s = fmaf(r[j], w3s[j], s);
        }
        g_w23[t] = s;
    }
    if (t == 127) {
        float be = 0.0f;
        for (int j = 0; j < H2; j++) be = fmaf(b2[j], w3s[j], be);
        g_beta = be;
    }
}

// ------------------- pipelined register-tiled GEMM (layer 1) -> fp16 rows --------
// g_bufH[node, :NP) = half(X[node,:] @ W). Fork-overlapped with CSR build.
template <int NQ, int TY, int TM, int KREAL, int KLOOP, int LDX,
          int NREAL, int NP, int MAXB>
__global__ void __launch_bounds__(NQ * TY, MAXB)
k_gemm_pipe(const float* __restrict__ X, const float* __restrict__ W, int n) {
    constexpr int KK = 16;
    constexpr int NT = (KLOOP + KK - 1) / KK;
    constexpr int BM = TY * TM;
    constexpr int BMP = BM + 2;
    constexpr int THREADS = NQ * TY;
    __shared__ __align__(16) float2 xs2[2][KK][BMP];
    __shared__ __align__(16) float4 ws4[2][KK][NQ];
    const int tx = threadIdx.x, ty = threadIdx.y;
    const int t = ty * NQ + tx;
    const int node0 = blockIdx.x * BM;

    unsigned long long acc[2 * TM];
#pragma unroll
    for (int h = 0; h < 2 * TM; h++) acc[h] = 0ull;

    auto load_tile = [&](int tile, int buf) {
        const int k0 = tile * KK;
        for (int idx = t; idx < BM * (KK / 4); idx += THREADS) {
            int nl = idx >> 2;
            int kq = idx & 3;
            int node = node0 + nl;
            float4 v = make_float4(0.f, 0.f, 0.f, 0.f);
            if (node < n)
                v = *(const float4*)(X + (size_t)node * LDX + k0 + kq * 4);
            xs2[buf][kq * 4 + 0][nl] = make_float2(v.x, v.x);
            xs2[buf][kq * 4 + 1][nl] = make_float2(v.y, v.y);
            xs2[buf][kq * 4 + 2][nl] = make_float2(v.z, v.z);
            xs2[buf][kq * 4 + 3][nl] = make_float2(v.w, v.w);
        }
        for (int idx = t; idx < KK * NQ; idx += THREADS) {
            int kk = idx / NQ;
            int q = idx - kk * NQ;
            int j = q * 4;
            int gk = k0 + kk;
            float4 w = make_float4(0.f, 0.f, 0.f, 0.f);
            if (gk < KREAL) {
                const float* wr = W + (size_t)gk * NREAL;
                if (j + 0 < NREAL) w.x = wr[j + 0];
                if (j + 1 < NREAL) w.y = wr[j + 1];
                if (j + 2 < NREAL) w.z = wr[j + 2];
                if (j + 3 < NREAL) w.w = wr[j + 3];
            }
            ws4[buf][kk][q] = w;
        }
    };

    load_tile(0, 0);
    __syncthreads();

    for (int tile = 0; tile < NT; tile++) {
        const int cur = tile & 1;
        if (tile + 1 < NT) load_tile(tile + 1, cur ^ 1);
#pragma unroll
        for (int kk = 0; kk < KK; kk++) {
            ulonglong2 w = *reinterpret_cast<const ulonglong2*>(&ws4[cur][kk][tx]);
#pragma unroll
            for (int j = 0; j < TM / 2; j++) {
                ulonglong2 xp = *reinterpret_cast<const ulonglong2*>(
                    &xs2[cur][kk][ty * TM + 2 * j]);
                FMA2(acc[4 * j + 0], xp.x, w.x, acc[4 * j + 0]);
                FMA2(acc[4 * j + 1], xp.x, w.y, acc[4 * j + 1]);
                FMA2(acc[4 * j + 2], xp.y, w.x, acc[4 * j + 2]);
                FMA2(acc[4 * j + 3], xp.y, w.y, acc[4 * j + 3]);
            }
        }
        __syncthreads();
    }

    // epilogue: convert this thread's quad (4 cols) of each node to half2 pair
#pragma unroll
    for (int m = 0; m < TM; m++) {
        int node = node0 + ty * TM + m;
        if (node < n) {
            float4 o;
            upk2(o.x, o.y, acc[2 * m]);
            upk2(o.z, o.w, acc[2 * m + 1]);
            __half2 h0 = __floats2half2_rn(o.x, o.y);
            __half2 h1 = __floats2half2_rn(o.z, o.w);
            uint2 pk = make_uint2(*(unsigned*)&h0, *(unsigned*)&h1);
            *(uint2*)(g_bufH + (size_t)node * NP1 + tx * 4) = pk;
        }
    }
}

// ------------------- gather layer 1 (fp16 rows): 9 threads/node, 8 cols each -----
// g_bufB[i,:] = relu( dinv_i*(sum_s dinv_s*xw[s,:] + dinv_i*xw[i,:]) + b ), fp32 out
__global__ void __launch_bounds__(256)
k_gather_h(const float* __restrict__ b, int n) {
    constexpr int NC = NP1 / 8;  // 9 uint4 chunks per row
    const int gt = blockIdx.x * blockDim.x + threadIdx.x;
    const int node = gt / NC;
    const int lane = gt - node * NC;  // 0..8
    if (node >= n) return;
    const uint4* __restrict__ xw = (const uint4*)g_bufH;  // row stride NC chunks

    float a0[8], a1[8];
#pragma unroll
    for (int j = 0; j < 8; j++) { a0[j] = 0.f; a1[j] = 0.f; }

    const int beg = g_rowoff[node];
    const int end = g_rowoff[node + 1];
    int e = beg;

    auto accum = [&](float* a, float w, uint4 v) {
        const __half2* h = (const __half2*)&v;
#pragma unroll
        for (int q = 0; q < 4; q++) {
            float2 f = __half22float2(h[q]);
            a[2 * q + 0] = fmaf(w, f.x, a[2 * q + 0]);
            a[2 * q + 1] = fmaf(w, f.y, a[2 * q + 1]);
        }
    };

    for (; e + 3 < end; e += 4) {
        int s0 = g_csr[e];
        int s1 = g_csr[e + 1];
        int s2 = g_csr[e + 2];
        int s3 = g_csr[e + 3];
        float w0 = __ldg(&g_dinv[s0]);
        float w1 = __ldg(&g_dinv[s1]);
        float w2 = __ldg(&g_dinv[s2]);
        float w3 = __ldg(&g_dinv[s3]);
        uint4 v0 = __ldg(&xw[(size_t)s0 * NC + lane]);
        uint4 v1 = __ldg(&xw[(size_t)s1 * NC + lane]);
        uint4 v2 = __ldg(&xw[(size_t)s2 * NC + lane]);
        uint4 v3 = __ldg(&xw[(size_t)s3 * NC + lane]);
        accum(a0, w0, v0);
        accum(a1, w1, v1);
        accum(a0, w2, v2);
        accum(a1, w3, v3);
    }
    for (; e < end; e++) {
        int s0 = g_csr[e];
        float w0 = __ldg(&g_dinv[s0]);
        uint4 v0 = __ldg(&xw[(size_t)s0 * NC + lane]);
        accum(a0, w0, v0);
    }
    const float di = g_dinv[node];
    {
        uint4 vi = __ldg(&xw[(size_t)node * NC + lane]);
        accum(a1, di, vi);
    }
    const int c = lane * 8;
    float r[8];
#pragma unroll
    for (int j = 0; j < 8; j++) {
        float bv = (c + j < H1) ? __ldg(&b[c + j]) : 0.0f;
        float v = fmaf(di, a0[j] + a1[j], bv);
        v = fmaxf(v, 0.0f);               // relu
        if (c + j >= H1) v = 0.0f;        // pad col stays zero
        r[j] = v;
    }
    float* o = (float*)g_bufB + (size_t)node * NP1 + c;
    *(float4*)(o + 0) = make_float4(r[0], r[1], r[2], r[3]);
    *(float4*)(o + 4) = make_float4(r[4], r[5], r[6], r[7]);
}

// ------------------- GEMV: v[node] = h1[node,:] . w23  (bufB -> bufA) ------------
__global__ void __launch_bounds__(256)
k_gemv(int n) {
    constexpr int BM = 256, KK = 24, KLOOP = NP1;
    __shared__ float xs[KK][BM + 1];
    __shared__ float ws[KLOOP];
    const float* X = (const float*)g_bufB;
    const int t = threadIdx.x;
    const int node0 = blockIdx.x * BM;
    if (t < KLOOP) ws[t] = g_w23[t];
    __syncthreads();
    float acc = 0.0f;
    for (int k0 = 0; k0 < KLOOP; k0 += KK) {
        for (int idx = t; idx < BM * KK; idx += 256) {
            int nl = idx / KK;
            int kk = idx - nl * KK;
            int node = node0 + nl;
            xs[kk][nl] = (node < n) ? X[(size_t)node * NP1 + k0 + kk] : 0.0f;
        }
        __syncthreads();
#pragma unroll
        for (int kk = 0; kk < KK; kk++) acc = fmaf(xs[kk][t], ws[k0 + kk], acc);
        __syncthreads();
    }
    const int node = node0 + t;
    if (node < n) g_bufA[node] = acc;
}

// ------------------- scalar gather (two phases) -----------------------------------
// PHASE 0: t = Anorm . v + beta      (g_bufA -> g_bufB)
// PHASE 1: out = Anorm . t + b[0]    (g_bufB -> out)
template <int PHASE>
__global__ void __launch_bounds__(256)
k_gather_scalar(const float* __restrict__ b, float* __restrict__ out, int n) {
    const int node = (blockIdx.x * blockDim.x + threadIdx.x) >> 5;
    if (node >= n) return;
    const int lane = threadIdx.x & 31;
    const float* y = (PHASE == 0) ? (const float*)g_bufA : (const float*)g_bufB;
    const int beg = g_rowoff[node];
    const int end = g_rowoff[node + 1];
    float acc = 0.0f;
    for (int e = beg + lane; e < end; e += 32) {
        int s = g_csr[e];
        acc = fmaf(__ldg(&g_dinv[s]), __ldg(&y[s]), acc);
    }
#pragma unroll
    for (int off = 16; off; off >>= 1) acc += __shfl_down_sync(0xffffffffu, acc, off);
    if (lane == 0) {
        float di = g_dinv[node];
        float bias = (PHASE == 0) ? g_beta : __ldg(&b[0]);
        float r = di * (acc + di * y[node]) + bias;
        if (PHASE == 0) ((float*)g_bufB)[node] = r;
        else out[node] = r;
    }
}

// ------------------- launcher: fork CSR build || layer-1 GEMM ---------------------
extern "C" void kernel_launch(void* const* d_in, const int* in_sizes, int n_in,
                              void* d_out, int out_size) {
    const float* x   = (const float*)d_in[0];
    const void*  ei  = d_in[1];
    const float* W1  = (const float*)d_in[2];
    const float* b1  = (const float*)d_in[3];
    const float* W2  = (const float*)d_in[4];
    const float* b2  = (const float*)d_in[5];
    const float* W3  = (const float*)d_in[6];
    const float* b3  = (const float*)d_in[7];
    float*       out = (float*)d_out;

    const int n = in_sizes[0] / IN_C;
    const int E = in_sizes[1] / 2;

    const int TB = 256;
    const int nb_nodes = (n + TB - 1) / TB;
    const int nb_edges = (E + TB - 1) / TB;
    const int nb_warps = (n * 32 + TB - 1) / TB;
    const int nb_scan  = (n + 1023) / 1024;
    const int nb_gemm1 = (n + 111) / 112;  // NQ=18 x TY=14, TM=8 -> BM=112
    const int nb_gemv  = (n + 255) / 256;
    const int nb_gath1 = ((long long)n * (NP1 / 8) + TB - 1) / TB;  // 9 thr/node

    // One-time side stream + events (created on the uncaptured correctness call).
    static cudaStream_t sB = nullptr;
    static cudaEvent_t evFork = nullptr, evJoin = nullptr;
    if (sB == nullptr) {
        cudaStreamCreateWithFlags(&sB, cudaStreamNonBlocking);
        cudaEventCreateWithFlags(&evFork, cudaEventDisableTiming);
        cudaEventCreateWithFlags(&evJoin, cudaEventDisableTiming);
    }

    // main: init (zeros deg, sniffs dtype)
    k_init_deg<<<nb_nodes, TB>>>((const int*)ei, E, n);           // 0
    cudaEventRecord(evFork, 0);
    cudaStreamWaitEvent(sB, evFork, 0);

    // side stream: CSR build part 1
    k_deg_count<<<nb_edges, TB, 0, sB>>>(ei, E, n);               // 1
    k_scan1<<<nb_scan, 1024, 0, sB>>>(n);                         // 2

    // main: layer-1 GEMM runs CONCURRENTLY with the CSR build
    k_gemm_pipe<18, 14, 8, IN_C, IN_C, IN_C, H1, NP1, 3>
        <<<nb_gemm1, dim3(18, 14)>>>(x, W1, n);                   // 3 <- profiled
    k_w23<<<1, 128>>>(W2, W3, b2);                                // 4 (main)

    // side stream: CSR build part 2
    k_scan2<<<1, 256, 0, sB>>>(nb_scan);                          // 5
    k_scan3<<<nb_scan, 1024, 0, sB>>>(n);                         // 6
    k_fill<<<nb_edges, TB, 0, sB>>>(E);                           // 7
    cudaEventRecord(evJoin, sB);

    // join: gathers need both CSR and gemm output
    cudaStreamWaitEvent(0, evJoin, 0);

    // Layer 1 gather (+bias+relu), fp16 rows: bufH -> bufB (fp32, stride 72)
    k_gather_h<<<nb_gath1, TB>>>(b1, n);

    // Collapsed layers 2+3:
    k_gemv<<<nb_gemv, 256>>>(n);                                // v -> bufA
    k_gather_scalar<0><<<nb_warps, TB>>>(nullptr, nullptr, n);  // t -> bufB
    k_gather_scalar<1><<<nb_warps, TB>>>(b3, out, n);           // out
}

// round 14
// speedup vs baseline: 1.8042x; 1.1011x over previous
#include <cuda_runtime.h>
#include <cuda_fp16.h>
#include <math.h>

// Problem constants (from reference)
#define N_NODES_MAX 100000
#define E_MAX       1600000
#define IN_C 128
#define H1   71
#define H2   82
#define NP1  72   // H1 padded (18 quads / 9 half-uint4 chunks)

// ------------------- device scratch (static, no allocation) -------------------
__device__ int   g_is64;
__device__ int   g_deg[N_NODES_MAX];
__device__ float g_dinv[N_NODES_MAX];
__device__ int   g_rowoff[N_NODES_MAX + 1];
__device__ int   g_cursor[N_NODES_MAX];
__device__ int   g_csr[E_MAX];
__device__ int   g_src[E_MAX];
__device__ int   g_dst[E_MAX];
__device__ int   g_bsum[256];
__device__ float g_w23[NP1];   // W2 @ W3 (padded with zeros)
__device__ float g_beta;       // b2 . W3
__device__ __align__(16) __half g_bufH[(size_t)N_NODES_MAX * NP1];  // xw rows (fp16)
__device__ float g_v[N_NODES_MAX];   // v = h1 . w23
__device__ float g_t[N_NODES_MAX];   // t = Anorm.v + beta

// ------------------- packed f32x2 helpers -------------------
__device__ __forceinline__ void upk2(float& lo, float& hi, unsigned long long v) {
    asm("mov.b64 {%0, %1}, %2;" : "=f"(lo), "=f"(hi) : "l"(v));
}
#define FMA2(d, a, b, c) \
    asm("fma.rn.f32x2 %0, %1, %2, %3;" : "=l"(d) : "l"(a), "l"(b), "l"(c))

// ------------------- setup kernels -------------------
__global__ void k_init_deg(const int* __restrict__ ei32, int E, int n) {
    int i = blockIdx.x * blockDim.x + threadIdx.x;
    if (i < n) g_deg[i] = 0;
    if (blockIdx.x == 0 && threadIdx.x == 0) {
        // dtype sniff: int64 indices < 1e5 have zero odd words
        int all0 = 1;
        int m = (E > 64) ? 64 : E;
        for (int q = 0; q < m; q++)
            if (ei32[2 * q + 1] != 0) { all0 = 0; break; }
        g_is64 = all0;
    }
}

__global__ void k_deg_count(const void* __restrict__ ei, int E, int n) {
    int i = blockIdx.x * blockDim.x + threadIdx.x;
    if (i < E) {
        int s, d;
        if (g_is64) {
            s = (int)((const long long*)ei)[i];
            d = (int)((const long long*)ei)[(size_t)E + i];
        } else {
            s = ((const int*)ei)[i];
            d = ((const int*)ei)[(size_t)E + i];
        }
        s = min(max(s, 0), n - 1);
        d = min(max(d, 0), n - 1);
        g_src[i] = s;
        g_dst[i] = d;
        atomicAdd(&g_deg[d], 1);
    }
}

// layer 2+3 collapse: w23 = W2 @ W3 (zero-padded), beta = b2 . W3
__global__ void k_w23(const float* __restrict__ W2, const float* __restrict__ W3,
                      const float* __restrict__ b2) {
    __shared__ float w3s[H2];
    int t = threadIdx.x;
    if (t < H2) w3s[t] = W3[t];
    __syncthreads();
    if (t < NP1) {
        float s = 0.0f;
        if (t < H1) {
            const float* r = W2 + (size_t)t * H2;
#pragma unroll 2
            for (int j = 0; j < H2; j++) s = fmaf(r[j], w3s[j], s);
        }
        g_w23[t] = s;
    }
    if (t == 127) {
        float be = 0.0f;
        for (int j = 0; j < H2; j++) be = fmaf(b2[j], w3s[j], be);
        g_beta = be;
    }
}

// pass 1: per-block (1024 elems) sums of deg; also compute dinv.
__global__ void __launch_bounds__(1024) k_scan1(int n) {
    __shared__ int wsum[32];
    int t = threadIdx.x, lane = t & 31, wid = t >> 5;
    int i = blockIdx.x * 1024 + t;
    int v = (i < n) ? g_deg[i] : 0;
    if (i < n) g_dinv[i] = rsqrtf((float)v + 1.0f);
    int x = v;
#pragma unroll
    for (int off = 16; off; off >>= 1) x += __shfl_down_sync(0xffffffffu, x, off);
    if (lane == 0) wsum[wid] = x;
    __syncthreads();
    if (wid == 0) {
        int y = wsum[lane];
#pragma unroll
        for (int off = 16; off; off >>= 1) y += __shfl_down_sync(0xffffffffu, y, off);
        if (lane == 0) g_bsum[blockIdx.x] = y;
    }
}

// pass 2+3 fused: each block computes its own bsum prefix, then local scan.
__global__ void __launch_bounds__(1024) k_scan3(int n, int nb) {
    __shared__ int wsum[32];
    __shared__ int s_base;
    int t = threadIdx.x, lane = t & 31, wid = t >> 5;
    // warp 0: prefix of bsum[0..blockIdx) via strided loads + shfl reduce
    if (wid == 0) {
        int s = 0;
        for (int i = lane; i < blockIdx.x; i += 32) s += g_bsum[i];
#pragma unroll
        for (int off = 16; off; off >>= 1) s += __shfl_down_sync(0xffffffffu, s, off);
        if (lane == 0) s_base = s;
    }
    int i = blockIdx.x * 1024 + t;
    int v = (i < n) ? g_deg[i] : 0;
    int x = v;
#pragma unroll
    for (int off = 1; off < 32; off <<= 1) {
        int y = __shfl_up_sync(0xffffffffu, x, off);
        if (lane >= off) x += y;
    }
    if (lane == 31) wsum[wid] = x;
    __syncthreads();
    if (wid == 0) {
        int w = wsum[lane];
        int xx = w;
#pragma unroll
        for (int off = 1; off < 32; off <<= 1) {
            int y = __shfl_up_sync(0xffffffffu, xx, off);
            if (lane >= off) xx += y;
        }
        wsum[lane] = xx - w;
    }
    __syncthreads();
    int excl = s_base + wsum[wid] + (x - v);
    if (i < n) {
        g_rowoff[i] = excl;
        g_cursor[i] = excl;
    }
    if (i == n - 1) g_rowoff[n] = excl + v;
}

__global__ void k_fill(int E) {
    int i = blockIdx.x * blockDim.x + threadIdx.x;
    if (i < E) {
        int d = g_dst[i];
        int p = atomicAdd(&g_cursor[d], 1);
        g_csr[p] = g_src[i];
    }
}

// ------------------- pipelined register-tiled GEMM (layer 1) -> fp16 rows --------
// g_bufH[node, :NP) = half(X[node,:] @ W). Fork-overlapped with CSR build.
template <int NQ, int TY, int TM, int KREAL, int KLOOP, int LDX,
          int NREAL, int NP, int MAXB>
__global__ void __launch_bounds__(NQ * TY, MAXB)
k_gemm_pipe(const float* __restrict__ X, const float* __restrict__ W, int n) {
    constexpr int KK = 16;
    constexpr int NT = (KLOOP + KK - 1) / KK;
    constexpr int BM = TY * TM;
    constexpr int BMP = BM + 2;
    constexpr int THREADS = NQ * TY;
    __shared__ __align__(16) float2 xs2[2][KK][BMP];
    __shared__ __align__(16) float4 ws4[2][KK][NQ];
    const int tx = threadIdx.x, ty = threadIdx.y;
    const int t = ty * NQ + tx;
    const int node0 = blockIdx.x * BM;

    unsigned long long acc[2 * TM];
#pragma unroll
    for (int h = 0; h < 2 * TM; h++) acc[h] = 0ull;

    auto load_tile = [&](int tile, int buf) {
        const int k0 = tile * KK;
        for (int idx = t; idx < BM * (KK / 4); idx += THREADS) {
            int nl = idx >> 2;
            int kq = idx & 3;
            int node = node0 + nl;
            float4 v = make_float4(0.f, 0.f, 0.f, 0.f);
            if (node < n)
                v = *(const float4*)(X + (size_t)node * LDX + k0 + kq * 4);
            xs2[buf][kq * 4 + 0][nl] = make_float2(v.x, v.x);
            xs2[buf][kq * 4 + 1][nl] = make_float2(v.y, v.y);
            xs2[buf][kq * 4 + 2][nl] = make_float2(v.z, v.z);
            xs2[buf][kq * 4 + 3][nl] = make_float2(v.w, v.w);
        }
        for (int idx = t; idx < KK * NQ; idx += THREADS) {
            int kk = idx / NQ;
            int q = idx - kk * NQ;
            int j = q * 4;
            int gk = k0 + kk;
            float4 w = make_float4(0.f, 0.f, 0.f, 0.f);
            if (gk < KREAL) {
                const float* wr = W + (size_t)gk * NREAL;
                if (j + 0 < NREAL) w.x = wr[j + 0];
                if (j + 1 < NREAL) w.y = wr[j + 1];
                if (j + 2 < NREAL) w.z = wr[j + 2];
                if (j + 3 < NREAL) w.w = wr[j + 3];
            }
            ws4[buf][kk][q] = w;
        }
    };

    load_tile(0, 0);
    __syncthreads();

    for (int tile = 0; tile < NT; tile++) {
        const int cur = tile & 1;
        if (tile + 1 < NT) load_tile(tile + 1, cur ^ 1);
#pragma unroll
        for (int kk = 0; kk < KK; kk++) {
            ulonglong2 w = *reinterpret_cast<const ulonglong2*>(&ws4[cur][kk][tx]);
#pragma unroll
            for (int j = 0; j < TM / 2; j++) {
                ulonglong2 xp = *reinterpret_cast<const ulonglong2*>(
                    &xs2[cur][kk][ty * TM + 2 * j]);
                FMA2(acc[4 * j + 0], xp.x, w.x, acc[4 * j + 0]);
                FMA2(acc[4 * j + 1], xp.x, w.y, acc[4 * j + 1]);
                FMA2(acc[4 * j + 2], xp.y, w.x, acc[4 * j + 2]);
                FMA2(acc[4 * j + 3], xp.y, w.y, acc[4 * j + 3]);
            }
        }
        __syncthreads();
    }

#pragma unroll
    for (int m = 0; m < TM; m++) {
        int node = node0 + ty * TM + m;
        if (node < n) {
            float4 o;
            upk2(o.x, o.y, acc[2 * m]);
            upk2(o.z, o.w, acc[2 * m + 1]);
            __half2 h0 = __floats2half2_rn(o.x, o.y);
            __half2 h1 = __floats2half2_rn(o.z, o.w);
            uint2 pk = make_uint2(*(unsigned*)&h0, *(unsigned*)&h1);
            *(uint2*)(g_bufH + (size_t)node * NP1 + tx * 4) = pk;
        }
    }
}

// ------------------- fused gather + relu + gemv -----------------------------------
// v[i] = w23 . relu( dinv_i*(sum_s dinv_s*xw[s,:] + dinv_i*xw[i,:]) + b1 )
// Block = 252 threads = 28 nodes x 9 lanes (8 cols each). Lanes reduce via smem.
__global__ void __launch_bounds__(252)
k_gather_v(const float* __restrict__ b, int n) {
    constexpr int NC = NP1 / 8;          // 9 uint4 chunks per row
    constexpr int NODES = 252 / NC;      // 28 nodes per block
    __shared__ float w23s[NP1];
    __shared__ float vsum[NODES];
    const int tid = threadIdx.x;
    if (tid < NP1) w23s[tid] = g_w23[tid];
    if (tid < NODES) vsum[tid] = 0.0f;
    __syncthreads();

    const int nl = tid / NC;
    const int lane = tid - nl * NC;      // 0..8
    const int node = blockIdx.x * NODES + nl;
    if (node < n) {
        const uint4* __restrict__ xw = (const uint4*)g_bufH;

        float a0[8], a1[8];
#pragma unroll
        for (int j = 0; j < 8; j++) { a0[j] = 0.f; a1[j] = 0.f; }

        auto accum = [&](float* a, float w, uint4 v) {
            const __half2* h = (const __half2*)&v;
#pragma unroll
            for (int q = 0; q < 4; q++) {
                float2 f = __half22float2(h[q]);
                a[2 * q + 0] = fmaf(w, f.x, a[2 * q + 0]);
                a[2 * q + 1] = fmaf(w, f.y, a[2 * q + 1]);
            }
        };

        const int beg = g_rowoff[node];
        const int end = g_rowoff[node + 1];
        int e = beg;
        for (; e + 3 < end; e += 4) {
            int s0 = g_csr[e];
            int s1 = g_csr[e + 1];
            int s2 = g_csr[e + 2];
            int s3 = g_csr[e + 3];
            float w0 = __ldg(&g_dinv[s0]);
            float w1 = __ldg(&g_dinv[s1]);
            float w2 = __ldg(&g_dinv[s2]);
            float w3 = __ldg(&g_dinv[s3]);
            uint4 v0 = __ldg(&xw[(size_t)s0 * NC + lane]);
            uint4 v1 = __ldg(&xw[(size_t)s1 * NC + lane]);
            uint4 v2 = __ldg(&xw[(size_t)s2 * NC + lane]);
            uint4 v3 = __ldg(&xw[(size_t)s3 * NC + lane]);
            accum(a0, w0, v0);
            accum(a1, w1, v1);
            accum(a0, w2, v2);
            accum(a1, w3, v3);
        }
        for (; e < end; e++) {
            int s0 = g_csr[e];
            float w0 = __ldg(&g_dinv[s0]);
            uint4 v0 = __ldg(&xw[(size_t)s0 * NC + lane]);
            accum(a0, w0, v0);
        }
        const float di = g_dinv[node];
        {
            uint4 vi = __ldg(&xw[(size_t)node * NC + lane]);
            accum(a1, di, vi);
        }
        const int c = lane * 8;
        float partial = 0.0f;
#pragma unroll
        for (int j = 0; j < 8; j++) {
            float bv = (c + j < H1) ? __ldg(&b[c + j]) : 0.0f;
            float hv = fmaxf(fmaf(di, a0[j] + a1[j], bv), 0.0f);  // relu(h1)
            partial = fmaf(hv, w23s[c + j], partial);  // w23 pad = 0 kills pad cols
        }
        atomicAdd(&vsum[nl], partial);
    }
    __syncthreads();
    if (tid < NODES) {
        int nd = blockIdx.x * NODES + tid;
        if (nd < n) g_v[nd] = vsum[tid];
    }
}

// ------------------- scalar gather (two phases) -----------------------------------
// PHASE 0: t = Anorm . v + beta      (g_v -> g_t)
// PHASE 1: out = Anorm . t + b[0]    (g_t -> out)
template <int PHASE>
__global__ void __launch_bounds__(256)
k_gather_scalar(const float* __restrict__ b, float* __restrict__ out, int n) {
    const int node = (blockIdx.x * blockDim.x + threadIdx.x) >> 5;
    if (node >= n) return;
    const int lane = threadIdx.x & 31;
    const float* y = (PHASE == 0) ? (const float*)g_v : (const float*)g_t;
    const int beg = g_rowoff[node];
    const int end = g_rowoff[node + 1];
    float acc = 0.0f;
    for (int e = beg + lane; e < end; e += 32) {
        int s = g_csr[e];
        acc = fmaf(__ldg(&g_dinv[s]), __ldg(&y[s]), acc);
    }
#pragma unroll
    for (int off = 16; off; off >>= 1) acc += __shfl_down_sync(0xffffffffu, acc, off);
    if (lane == 0) {
        float di = g_dinv[node];
        float bias = (PHASE == 0) ? g_beta : __ldg(&b[0]);
        float r = di * (acc + di * y[node]) + bias;
        if (PHASE == 0) g_t[node] = r;
        else out[node] = r;
    }
}

// ------------------- launcher: fork CSR build || layer-1 GEMM ---------------------
extern "C" void kernel_launch(void* const* d_in, const int* in_sizes, int n_in,
                              void* d_out, int out_size) {
    const float* x   = (const float*)d_in[0];
    const void*  ei  = d_in[1];
    const float* W1  = (const float*)d_in[2];
    const float* b1  = (const float*)d_in[3];
    const float* W2  = (const float*)d_in[4];
    const float* b2  = (const float*)d_in[5];
    const float* W3  = (const float*)d_in[6];
    const float* b3  = (const float*)d_in[7];
    float*       out = (float*)d_out;

    const int n = in_sizes[0] / IN_C;
    const int E = in_sizes[1] / 2;

    const int TB = 256;
    const int nb_nodes = (n + TB - 1) / TB;
    const int nb_edges = (E + TB - 1) / TB;
    const int nb_warps = (n * 32 + TB - 1) / TB;
    const int nb_scan  = (n + 1023) / 1024;
    const int nb_gemm1 = (n + 111) / 112;  // NQ=18 x TY=14, TM=8 -> BM=112
    const int nb_gathv = (n + 27) / 28;    // 28 nodes per 252-thread block

    // One-time side stream + events (created on the uncaptured correctness call).
    static cudaStream_t sB = nullptr;
    static cudaEvent_t evFork = nullptr, evJoin = nullptr;
    if (sB == nullptr) {
        cudaStreamCreateWithFlags(&sB, cudaStreamNonBlocking);
        cudaEventCreateWithFlags(&evFork, cudaEventDisableTiming);
        cudaEventCreateWithFlags(&evJoin, cudaEventDisableTiming);
    }

    // main: init (zeros deg, sniffs dtype)
    k_init_deg<<<nb_nodes, TB>>>((const int*)ei, E, n);           // 0
    cudaEventRecord(evFork, 0);
    cudaStreamWaitEvent(sB, evFork, 0);

    // side stream: CSR build + w23
    k_deg_count<<<nb_edges, TB, 0, sB>>>(ei, E, n);               // 1
    k_w23<<<1, 128, 0, sB>>>(W2, W3, b2);                         // 2

    // main: layer-1 GEMM runs CONCURRENTLY with the CSR build
    k_gemm_pipe<18, 14, 8, IN_C, IN_C, IN_C, H1, NP1, 3>
        <<<nb_gemm1, dim3(18, 14)>>>(x, W1, n);                   // 3 <- profiled

    // side stream: scan + fill
    k_scan1<<<nb_scan, 1024, 0, sB>>>(n);                         // 4
    k_scan3<<<nb_scan, 1024, 0, sB>>>(n, nb_scan);                // 5
    k_fill<<<nb_edges, TB, 0, sB>>>(E);                           // 6
    cudaEventRecord(evJoin, sB);

    // join: gathers need both CSR and gemm output
    cudaStreamWaitEvent(0, evJoin, 0);

    // Fused gather+relu+gemv: bufH -> v
    k_gather_v<<<nb_gathv, 252>>>(b1, n);

    // Collapsed layers 2+3 propagation:
    k_gather_scalar<0><<<nb_warps, TB>>>(nullptr, nullptr, n);  // t
    k_gather_scalar<1><<<nb_warps, TB>>>(b3, out, n);           // out
}